// round 1
// baseline (speedup 1.0000x reference)
#include <cuda_runtime.h>
#include <math.h>
#include <stddef.h>

// ---------------- problem constants ----------------
#define NUSR 50000
#define NITM 20000
#define NEDG 400000
#define FIN0 128
#define FHID 256
#define NHEAD 4

// ---------------- device scratch (no allocs allowed) ----------------
__device__ float g_hu [(size_t)NUSR * FHID];   // current user features
__device__ float g_hi [(size_t)NITM * FHID];   // current item features
__device__ float g_hsu[(size_t)NUSR * FHID];   // projected user feats (hs for ui)
__device__ float g_hsi[(size_t)NITM * FHID];   // projected item feats (hs for iu)
__device__ float g_nu [(size_t)NUSR * FHID];   // aggregated user output (pre-BN)
__device__ float g_ni [(size_t)NITM * FHID];   // aggregated item output (pre-BN)
__device__ float g_el_u[NUSR * 4];
__device__ float g_el_i[NITM * 4];
__device__ float g_er_u[NUSR * 4];
__device__ float g_er_i[NITM * 4];
__device__ float g_alpha_i[(size_t)NEDG * 4];  // softmax weights, item-CSR order
__device__ float g_alpha_u[(size_t)NEDG * 4];  // softmax weights, user-CSR order
__device__ int   g_rp_i[NITM + 1];
__device__ int   g_rp_u[NUSR + 1];
__device__ int   g_srcs_i[NEDG];               // user idx per edge, grouped by item
__device__ int   g_srcs_u[NEDG];               // item idx per edge, grouped by user
__device__ int   g_cur_i[NITM];
__device__ int   g_cur_u[NUSR];
__device__ float g_V[FHID * NHEAD];            // collapsed W·A1 for er
__device__ float g_stats[2 * FHID];            // BN sum / sumsq

// ---------------- f32x2 helpers ----------------
__device__ __forceinline__ unsigned long long pk2(float lo, float hi) {
    unsigned long long r;
    asm("mov.b64 %0, {%1, %2};" : "=l"(r)
        : "r"(__float_as_uint(lo)), "r"(__float_as_uint(hi)));
    return r;
}
__device__ __forceinline__ void fma2(unsigned long long& acc,
                                     unsigned long long a, unsigned long long b) {
    asm("fma.rn.f32x2 %0, %1, %2, %0;" : "+l"(acc) : "l"(a), "l"(b));
}
__device__ __forceinline__ float2 upk2(unsigned long long v) {
    unsigned lo, hi;
    asm("mov.b64 {%0, %1}, %2;" : "=r"(lo), "=r"(hi) : "l"(v));
    return make_float2(__uint_as_float(lo), __uint_as_float(hi));
}

// ---------------- tiny utility kernels ----------------
__global__ void k_zeroi(int* p, int n) {
    int i = blockIdx.x * blockDim.x + threadIdx.x;
    if (i < n) p[i] = 0;
}
__global__ void k_zerof(float* p, int n) {
    int i = blockIdx.x * blockDim.x + threadIdx.x;
    if (i < n) p[i] = 0.f;
}
__global__ void k_copyi(const int* __restrict__ a, int* __restrict__ b, int n) {
    int i = blockIdx.x * blockDim.x + threadIdx.x;
    if (i < n) b[i] = a[i];
}

// ---------------- CSR construction ----------------
__global__ void k_count(const int* __restrict__ eu, const int* __restrict__ ei,
                        int* cu, int* ci) {
    int k = blockIdx.x * blockDim.x + threadIdx.x;
    if (k < NEDG) {
        atomicAdd(&ci[ei[k]], 1);
        atomicAdd(&cu[eu[k]], 1);
    }
}

__global__ void k_exscan(const int* __restrict__ cnt, int n, int* __restrict__ rp) {
    __shared__ int warpsum[32];
    __shared__ int s_carry;
    int tid = threadIdx.x;
    if (tid == 0) { s_carry = 0; rp[0] = 0; }
    __syncthreads();
    for (int base = 0; base < n; base += 1024) {
        int i = base + tid;
        int v = (i < n) ? cnt[i] : 0;
        int lane = tid & 31, w = tid >> 5;
        int x = v;
        #pragma unroll
        for (int o = 1; o < 32; o <<= 1) {
            int y = __shfl_up_sync(0xffffffffu, x, o);
            if (lane >= o) x += y;
        }
        if (lane == 31) warpsum[w] = x;
        __syncthreads();
        if (w == 0) {
            int t = warpsum[lane];
            #pragma unroll
            for (int o = 1; o < 32; o <<= 1) {
                int y = __shfl_up_sync(0xffffffffu, t, o);
                if (lane >= o) t += y;
            }
            warpsum[lane] = t;
        }
        __syncthreads();
        int incl = x + (w > 0 ? warpsum[w - 1] : 0) + s_carry;
        if (i < n) rp[i + 1] = incl;
        __syncthreads();
        if (tid == 1023) s_carry = incl;
        __syncthreads();
    }
}

__global__ void k_scatter(const int* __restrict__ eu, const int* __restrict__ ei,
                          int* cu, int* ci,
                          int* __restrict__ su, int* __restrict__ si) {
    int k = blockIdx.x * blockDim.x + threadIdx.x;
    if (k < NEDG) {
        int u = eu[k], it = ei[k];
        int p = atomicAdd(&ci[it], 1);
        si[p] = u;
        int q = atomicAdd(&cu[u], 1);
        su[q] = it;
    }
}

// ---------------- SGEMM: C[M,N] = A[M,K] @ B[K,N], fp32, f32x2 FMA ----------------
__global__ void __launch_bounds__(256, 2)
k_sgemm(const float* __restrict__ A, const float* __restrict__ B,
        float* __restrict__ C, int M, int K, int N) {
    __shared__ float As[8][132];   // padded: transposed A tile
    __shared__ float Bs[8][128];
    int tid = threadIdx.x;
    int bm = blockIdx.x * 128;
    int bn = blockIdx.y * 128;
    int tx = tid & 15, ty = tid >> 4;

    int arow = tid >> 1;
    int acol = (tid & 1) * 4;
    int brow = tid >> 5;
    int bcol = (tid & 31) * 4;

    unsigned long long acc[8][4];
    unsigned long long z = pk2(0.f, 0.f);
    #pragma unroll
    for (int i = 0; i < 8; i++)
        #pragma unroll
        for (int j = 0; j < 4; j++) acc[i][j] = z;

    for (int k0 = 0; k0 < K; k0 += 8) {
        float4 av;
        if (bm + arow < M)
            av = *(const float4*)(A + (size_t)(bm + arow) * K + k0 + acol);
        else
            av = make_float4(0.f, 0.f, 0.f, 0.f);
        As[acol + 0][arow] = av.x;
        As[acol + 1][arow] = av.y;
        As[acol + 2][arow] = av.z;
        As[acol + 3][arow] = av.w;
        float4 bv = *(const float4*)(B + (size_t)(k0 + brow) * N + bn + bcol);
        *(float4*)&Bs[brow][bcol] = bv;
        __syncthreads();
        #pragma unroll
        for (int k = 0; k < 8; k++) {
            float4 a0 = *(const float4*)&As[k][ty * 8];
            float4 a1 = *(const float4*)&As[k][ty * 8 + 4];
            float4 b0 = *(const float4*)&Bs[k][tx * 8];
            float4 b1 = *(const float4*)&Bs[k][tx * 8 + 4];
            unsigned long long bp[4];
            bp[0] = pk2(b0.x, b0.y); bp[1] = pk2(b0.z, b0.w);
            bp[2] = pk2(b1.x, b1.y); bp[3] = pk2(b1.z, b1.w);
            float aa[8] = {a0.x, a0.y, a0.z, a0.w, a1.x, a1.y, a1.z, a1.w};
            #pragma unroll
            for (int i = 0; i < 8; i++) {
                unsigned long long ap = pk2(aa[i], aa[i]);
                #pragma unroll
                for (int j = 0; j < 4; j++) fma2(acc[i][j], ap, bp[j]);
            }
        }
        __syncthreads();
    }
    #pragma unroll
    for (int i = 0; i < 8; i++) {
        int r = bm + ty * 8 + i;
        if (r < M) {
            float2 c0 = upk2(acc[i][0]), c1 = upk2(acc[i][1]);
            float2 c2 = upk2(acc[i][2]), c3 = upk2(acc[i][3]);
            float4 o0 = make_float4(c0.x, c0.y, c1.x, c1.y);
            float4 o1 = make_float4(c2.x, c2.y, c3.x, c3.y);
            float* cp = C + (size_t)r * N + bn + tx * 8;
            *(float4*)cp = o0;
            *(float4*)(cp + 4) = o1;
        }
    }
}

// ---------------- el[n,h] = sum_f-in-head hs[n,f]*A0[f] ----------------
__global__ void k_el(const float* __restrict__ hs, const float* __restrict__ A,
                     float* __restrict__ el, int n, int F) {
    int w = (blockIdx.x * blockDim.x + threadIdx.x) >> 5;
    int lane = threadIdx.x & 31;
    if (w >= n) return;
    int CH = F >> 5;
    const float* row = hs + (size_t)w * F + lane * CH;
    float p = 0.f;
    for (int c = 0; c < CH; c++) p += row[c] * A[lane * CH + c];
    p += __shfl_down_sync(0xffffffffu, p, 4, 8);
    p += __shfl_down_sync(0xffffffffu, p, 2, 8);
    p += __shfl_down_sync(0xffffffffu, p, 1, 8);
    if ((lane & 7) == 0) el[w * 4 + (lane >> 3)] = p;
}

// ---------------- V[k,h] = sum_d W[k, h*dh+d] * A1[h,d] ----------------
__global__ void k_collapseV(const float* __restrict__ W, const float* __restrict__ A,
                            float* __restrict__ V, int fin, int F, int dh) {
    int t = blockIdx.x * blockDim.x + threadIdx.x;
    if (t >= fin * NHEAD) return;
    int k = t >> 2, h = t & 3;
    const float* A1 = A + NHEAD * dh;
    float s = 0.f;
    for (int d = 0; d < dh; d++)
        s += W[(size_t)k * F + h * dh + d] * A1[h * dh + d];
    V[t] = s;
}

// ---------------- er[n,:] = X[n,:] @ V ----------------
__global__ void k_er(const float* __restrict__ X, const float4* __restrict__ V4,
                     float* __restrict__ er, int n, int fin) {
    int w = (blockIdx.x * blockDim.x + threadIdx.x) >> 5;
    int lane = threadIdx.x & 31;
    if (w >= n) return;
    const float* x = X + (size_t)w * fin;
    float a0 = 0.f, a1 = 0.f, a2 = 0.f, a3 = 0.f;
    for (int k = lane; k < fin; k += 32) {
        float xv = x[k];
        float4 v = V4[k];
        a0 += xv * v.x; a1 += xv * v.y; a2 += xv * v.z; a3 += xv * v.w;
    }
    #pragma unroll
    for (int o = 16; o; o >>= 1) {
        a0 += __shfl_xor_sync(0xffffffffu, a0, o);
        a1 += __shfl_xor_sync(0xffffffffu, a1, o);
        a2 += __shfl_xor_sync(0xffffffffu, a2, o);
        a3 += __shfl_xor_sync(0xffffffffu, a3, o);
    }
    if (lane == 0) {
        er[w * 4 + 0] = a0; er[w * 4 + 1] = a1;
        er[w * 4 + 2] = a2; er[w * 4 + 3] = a3;
    }
}

__device__ __forceinline__ float lrelu(float x, float s) { return x > 0.f ? x : s * x; }

// ---------------- segment softmax: alpha per edge (CSR order) ----------------
__global__ void k_attn(const int* __restrict__ rp, const int* __restrict__ srcs,
                       const float4* __restrict__ el4, const float4* __restrict__ er4,
                       float4* __restrict__ alpha4, int ndst) {
    int w = (blockIdx.x * blockDim.x + threadIdx.x) >> 5;
    int lane = threadIdx.x & 31;
    if (w >= ndst) return;
    int s0 = rp[w], s1 = rp[w + 1];
    if (s0 == s1) return;
    float4 er = er4[w];
    float m0 = -1e30f, m1 = -1e30f, m2 = -1e30f, m3 = -1e30f;
    for (int j = s0 + lane; j < s1; j += 32) {
        float4 e = el4[srcs[j]];
        m0 = fmaxf(m0, lrelu(e.x + er.x, 0.2f));
        m1 = fmaxf(m1, lrelu(e.y + er.y, 0.2f));
        m2 = fmaxf(m2, lrelu(e.z + er.z, 0.2f));
        m3 = fmaxf(m3, lrelu(e.w + er.w, 0.2f));
    }
    #pragma unroll
    for (int o = 16; o; o >>= 1) {
        m0 = fmaxf(m0, __shfl_xor_sync(0xffffffffu, m0, o));
        m1 = fmaxf(m1, __shfl_xor_sync(0xffffffffu, m1, o));
        m2 = fmaxf(m2, __shfl_xor_sync(0xffffffffu, m2, o));
        m3 = fmaxf(m3, __shfl_xor_sync(0xffffffffu, m3, o));
    }
    float z0 = 0.f, z1 = 0.f, z2 = 0.f, z3 = 0.f;
    for (int j = s0 + lane; j < s1; j += 32) {
        float4 e = el4[srcs[j]];
        z0 += expf(lrelu(e.x + er.x, 0.2f) - m0);
        z1 += expf(lrelu(e.y + er.y, 0.2f) - m1);
        z2 += expf(lrelu(e.z + er.z, 0.2f) - m2);
        z3 += expf(lrelu(e.w + er.w, 0.2f) - m3);
    }
    #pragma unroll
    for (int o = 16; o; o >>= 1) {
        z0 += __shfl_xor_sync(0xffffffffu, z0, o);
        z1 += __shfl_xor_sync(0xffffffffu, z1, o);
        z2 += __shfl_xor_sync(0xffffffffu, z2, o);
        z3 += __shfl_xor_sync(0xffffffffu, z3, o);
    }
    float i0 = 1.f / z0, i1 = 1.f / z1, i2 = 1.f / z2, i3 = 1.f / z3;
    for (int j = s0 + lane; j < s1; j += 32) {
        float4 e = el4[srcs[j]];
        float4 a;
        a.x = expf(lrelu(e.x + er.x, 0.2f) - m0) * i0;
        a.y = expf(lrelu(e.y + er.y, 0.2f) - m1) * i1;
        a.z = expf(lrelu(e.z + er.z, 0.2f) - m2) * i2;
        a.w = expf(lrelu(e.w + er.w, 0.2f) - m3) * i3;
        alpha4[j] = a;
    }
}

// ---------------- aggregation: out[d] = sum_e alpha (x) hs[src] ----------------
__global__ void k_aggr256(const int* __restrict__ rp, const int* __restrict__ srcs,
                          const float4* __restrict__ alpha4, const float* __restrict__ hs,
                          float* __restrict__ out, int ndst) {
    int w = (blockIdx.x * blockDim.x + threadIdx.x) >> 5;
    int lane = threadIdx.x & 31;
    if (w >= ndst) return;
    int s0 = rp[w], s1 = rp[w + 1];
    float4 acc0 = make_float4(0.f, 0.f, 0.f, 0.f);
    float4 acc1 = make_float4(0.f, 0.f, 0.f, 0.f);
    for (int j = s0; j < s1; j++) {
        int s = srcs[j];
        float4 al = alpha4[j];
        float a0 = (lane < 16) ? al.x : al.y;   // head of floats [lane*4 .. +3]
        float a1 = (lane < 16) ? al.z : al.w;   // head of floats [128+lane*4 .. +3]
        const float4* row = (const float4*)(hs + (size_t)s * 256);
        float4 v0 = row[lane];
        float4 v1 = row[lane + 32];
        acc0.x += a0 * v0.x; acc0.y += a0 * v0.y; acc0.z += a0 * v0.z; acc0.w += a0 * v0.w;
        acc1.x += a1 * v1.x; acc1.y += a1 * v1.y; acc1.z += a1 * v1.z; acc1.w += a1 * v1.w;
    }
    float4* o = (float4*)(out + (size_t)w * 256);
    o[lane] = acc0;
    o[lane + 32] = acc1;
}

__global__ void k_aggr128(const int* __restrict__ rp, const int* __restrict__ srcs,
                          const float4* __restrict__ alpha4, const float* __restrict__ hs,
                          float* __restrict__ out, int ndst) {
    int w = (blockIdx.x * blockDim.x + threadIdx.x) >> 5;
    int lane = threadIdx.x & 31;
    if (w >= ndst) return;
    int s0 = rp[w], s1 = rp[w + 1];
    float4 acc = make_float4(0.f, 0.f, 0.f, 0.f);
    for (int j = s0; j < s1; j++) {
        int s = srcs[j];
        float4 al = alpha4[j];
        float a = (lane & 8) ? ((lane & 16) ? al.w : al.y)
                             : ((lane & 16) ? al.z : al.x);  // dh=32
        const float4* row = (const float4*)(hs + (size_t)s * 128);
        float4 v = row[lane];
        acc.x += a * v.x; acc.y += a * v.y; acc.z += a * v.z; acc.w += a * v.w;
    }
    ((float4*)(out + (size_t)w * 128))[lane] = acc;
}

// ---------------- BatchNorm ----------------
__global__ void k_bnstats(const float* __restrict__ x, float* __restrict__ stats, int n) {
    int c = threadIdx.x;   // 256 threads, one per column
    float s = 0.f, q = 0.f;
    for (int r = blockIdx.x; r < n; r += gridDim.x) {
        float v = x[(size_t)r * 256 + c];
        s += v;
        q += v * v;
    }
    atomicAdd(&stats[c], s);
    atomicAdd(&stats[256 + c], q);
}

__global__ void k_bnapply(const float* __restrict__ x, float* __restrict__ y,
                          const float* __restrict__ bn, const float* __restrict__ stats,
                          int L, int n, int use_tanh) {
    int c = threadIdx.x;
    float mu = stats[c] / (float)n;
    float var = stats[256 + c] / (float)n - mu * mu;
    float gamma = bn[(L * 2 + 0) * 256 + c];
    float beta  = bn[(L * 2 + 1) * 256 + c];
    float sc = gamma * rsqrtf(var + 1e-5f);
    float sh = beta - mu * sc;
    for (int r = blockIdx.x; r < n; r += gridDim.x) {
        size_t idx = (size_t)r * 256 + c;
        float v = sc * x[idx] + sh;
        y[idx] = use_tanh ? tanhf(v) : (v > 0.f ? v : 0.01f * v);
    }
}

// ---------------- host orchestration ----------------
static inline int wgrid(int nwarp) { return (nwarp * 32 + 255) / 256; }

struct Ptrs {
    float *hu, *hi, *hsu, *hsi, *nu, *ni;
    float *el_u, *el_i, *er_u, *er_i, *alpha_i, *alpha_u, *V, *stats;
    int *rp_i, *rp_u, *srcs_i, *srcs_u, *cur_i, *cur_u;
};

static void get_ptrs(Ptrs& p) {
    cudaGetSymbolAddress((void**)&p.hu, g_hu);
    cudaGetSymbolAddress((void**)&p.hi, g_hi);
    cudaGetSymbolAddress((void**)&p.hsu, g_hsu);
    cudaGetSymbolAddress((void**)&p.hsi, g_hsi);
    cudaGetSymbolAddress((void**)&p.nu, g_nu);
    cudaGetSymbolAddress((void**)&p.ni, g_ni);
    cudaGetSymbolAddress((void**)&p.el_u, g_el_u);
    cudaGetSymbolAddress((void**)&p.el_i, g_el_i);
    cudaGetSymbolAddress((void**)&p.er_u, g_er_u);
    cudaGetSymbolAddress((void**)&p.er_i, g_er_i);
    cudaGetSymbolAddress((void**)&p.alpha_i, g_alpha_i);
    cudaGetSymbolAddress((void**)&p.alpha_u, g_alpha_u);
    cudaGetSymbolAddress((void**)&p.V, g_V);
    cudaGetSymbolAddress((void**)&p.stats, g_stats);
    cudaGetSymbolAddress((void**)&p.rp_i, g_rp_i);
    cudaGetSymbolAddress((void**)&p.rp_u, g_rp_u);
    cudaGetSymbolAddress((void**)&p.srcs_i, g_srcs_i);
    cudaGetSymbolAddress((void**)&p.srcs_u, g_srcs_u);
    cudaGetSymbolAddress((void**)&p.cur_i, g_cur_i);
    cudaGetSymbolAddress((void**)&p.cur_u, g_cur_u);
}

static void sgemm(const float* A, const float* B, float* C, int M, int K, int N) {
    dim3 g((M + 127) / 128, N / 128);
    k_sgemm<<<g, 256>>>(A, B, C, M, K, N);
}

// one relation-layer pair (both directions)
static void relation_pass(const Ptrs& p, const float* cu, const float* ci,
                          const float* Wui, const float* Aui,
                          const float* Wiu, const float* Aiu,
                          int fin, int F, int dh,
                          float* outu, float* outi) {
    sgemm(cu, Wui, p.hsu, NUSR, fin, F);
    sgemm(ci, Wiu, p.hsi, NITM, fin, F);
    k_el<<<wgrid(NUSR), 256>>>(p.hsu, Aui, p.el_u, NUSR, F);
    k_el<<<wgrid(NITM), 256>>>(p.hsi, Aiu, p.el_i, NITM, F);
    k_collapseV<<<(fin * 4 + 255) / 256, 256>>>(Wui, Aui, p.V, fin, F, dh);
    k_er<<<wgrid(NITM), 256>>>(ci, (const float4*)p.V, p.er_i, NITM, fin);
    k_collapseV<<<(fin * 4 + 255) / 256, 256>>>(Wiu, Aiu, p.V, fin, F, dh);
    k_er<<<wgrid(NUSR), 256>>>(cu, (const float4*)p.V, p.er_u, NUSR, fin);
    k_attn<<<wgrid(NITM), 256>>>(p.rp_i, p.srcs_i, (const float4*)p.el_u,
                                 (const float4*)p.er_i, (float4*)p.alpha_i, NITM);
    k_attn<<<wgrid(NUSR), 256>>>(p.rp_u, p.srcs_u, (const float4*)p.el_i,
                                 (const float4*)p.er_u, (float4*)p.alpha_u, NUSR);
    if (F == 256) {
        k_aggr256<<<wgrid(NITM), 256>>>(p.rp_i, p.srcs_i, (const float4*)p.alpha_i,
                                        p.hsu, outi, NITM);
        k_aggr256<<<wgrid(NUSR), 256>>>(p.rp_u, p.srcs_u, (const float4*)p.alpha_u,
                                        p.hsi, outu, NUSR);
    } else {
        k_aggr128<<<wgrid(NITM), 256>>>(p.rp_i, p.srcs_i, (const float4*)p.alpha_i,
                                        p.hsu, outi, NITM);
        k_aggr128<<<wgrid(NUSR), 256>>>(p.rp_u, p.srcs_u, (const float4*)p.alpha_u,
                                        p.hsi, outu, NUSR);
    }
}

extern "C" void kernel_launch(void* const* d_in, const int* in_sizes, int n_in,
                              void* d_out, int out_size) {
    Ptrs p;
    get_ptrs(p);

    const float* x_user = (const float*)d_in[0];
    const float* x_item = (const float*)d_in[1];
    const int*   eu     = (const int*)d_in[2];
    const int*   ei     = (const int*)d_in[3];

    // resolve input ordering: dict order has A0_ui (512 elems) at slot 5
    bool dictOrder = (in_sizes[5] < 10000);
    const float *Wui[4], *Aui[4], *Wiu[4], *Aiu[4];
    for (int L = 0; L < 4; L++) {
        if (dictOrder) {
            Wui[L] = (const float*)d_in[4 + L * 4 + 0];
            Aui[L] = (const float*)d_in[4 + L * 4 + 1];
            Wiu[L] = (const float*)d_in[4 + L * 4 + 2];
            Aiu[L] = (const float*)d_in[4 + L * 4 + 3];
        } else {
            Wui[L] = (const float*)d_in[4 + L * 4 + 0];
            Wiu[L] = (const float*)d_in[4 + L * 4 + 1];
            Aui[L] = (const float*)d_in[4 + L * 4 + 2];
            Aiu[L] = (const float*)d_in[4 + L * 4 + 3];
        }
    }
    const float* bn_u = (const float*)d_in[20];
    const float* bn_i = (const float*)d_in[21];
    float* out = (float*)d_out;

    // ---- CSR build (per replay; cheap) ----
    k_zeroi<<<(NUSR + 255) / 256, 256>>>(p.cur_u, NUSR);
    k_zeroi<<<(NITM + 255) / 256, 256>>>(p.cur_i, NITM);
    k_count<<<(NEDG + 255) / 256, 256>>>(eu, ei, p.cur_u, p.cur_i);
    k_exscan<<<1, 1024>>>(p.cur_i, NITM, p.rp_i);
    k_exscan<<<1, 1024>>>(p.cur_u, NUSR, p.rp_u);
    k_copyi<<<(NITM + 255) / 256, 256>>>(p.rp_i, p.cur_i, NITM);
    k_copyi<<<(NUSR + 255) / 256, 256>>>(p.rp_u, p.cur_u, NUSR);
    k_scatter<<<(NEDG + 255) / 256, 256>>>(eu, ei, p.cur_u, p.cur_i, p.srcs_u, p.srcs_i);

    // ---- hidden layers 0..2 ----
    const float* cu = x_user;
    const float* ci = x_item;
    int fin = FIN0;
    for (int L = 0; L < 3; L++) {
        relation_pass(p, cu, ci, Wui[L], Aui[L], Wiu[L], Aiu[L],
                      fin, 256, 64, p.nu, p.ni);
        int tanh_act = (L == 2) ? 1 : 0;
        k_zerof<<<2, 256>>>(p.stats, 512);
        k_bnstats<<<256, 256>>>(p.nu, p.stats, NUSR);
        k_bnapply<<<256, 256>>>(p.nu, p.hu, bn_u, p.stats, L, NUSR, tanh_act);
        k_zerof<<<2, 256>>>(p.stats, 512);
        k_bnstats<<<256, 256>>>(p.ni, p.stats, NITM);
        k_bnapply<<<256, 256>>>(p.ni, p.hi, bn_i, p.stats, L, NITM, tanh_act);
        cu = p.hu;
        ci = p.hi;
        fin = FHID;
    }

    // ---- output layer 3: F=128, dh=32, no BN/act; write straight into d_out ----
    relation_pass(p, cu, ci, Wui[3], Aui[3], Wiu[3], Aiu[3],
                  256, 128, 32,
                  out /* users at rows [0,NU) */,
                  out + (size_t)NUSR * 128 /* items at rows [NU,NU+NI) */);
    (void)n_in; (void)out_size;
}

// round 3
// speedup vs baseline: 1.3023x; 1.3023x over previous
#include <cuda_runtime.h>
#include <cuda_bf16.h>
#include <math.h>
#include <stddef.h>
#include <stdint.h>

// ---------------- problem constants ----------------
#define NUSR 50000
#define NITM 20000
#define NEDG 400000
#define FIN0 128
#define FHID 256
#define NHEAD 4

// ---------------- device scratch (no allocs allowed) ----------------
__device__ float g_hu [(size_t)NUSR * FHID];
__device__ float g_hi [(size_t)NITM * FHID];
__device__ float g_hsu[(size_t)NUSR * FHID];
__device__ float g_hsi[(size_t)NITM * FHID];
__device__ float g_nu [(size_t)NUSR * FHID];
__device__ float g_ni [(size_t)NITM * FHID];
__device__ float g_el_u[NUSR * 4];
__device__ float g_el_i[NITM * 4];
__device__ float g_er_u[NUSR * 4];
__device__ float g_er_i[NITM * 4];
__device__ float g_alpha_i[(size_t)NEDG * 4];
__device__ float g_alpha_u[(size_t)NEDG * 4];
__device__ int   g_rp_i[NITM + 1];
__device__ int   g_rp_u[NUSR + 1];
__device__ int   g_srcs_i[NEDG];
__device__ int   g_srcs_u[NEDG];
__device__ int   g_cur_i[NITM];
__device__ int   g_cur_u[NUSR];
__device__ float g_V[FHID * NHEAD];
__device__ float g_stats[2 * FHID];
__device__ int   g_part[64];
__device__ __nv_bfloat16 g_Bh[FHID * FHID];   // weight hi bf16, [K,N] layout
__device__ __nv_bfloat16 g_Bl[FHID * FHID];   // weight lo bf16, [K,N] layout

// ---------------- mma/ldmatrix helpers (baseline PTX, no 'a' features) ----------
__device__ __forceinline__ uint32_t smem_u32(const void* p) {
    uint32_t a;
    asm("{ .reg .u64 t; cvta.to.shared.u64 t, %1; cvt.u32.u64 %0, t; }"
        : "=r"(a) : "l"(p));
    return a;
}
__device__ __forceinline__ void ldsm4(uint32_t* r, uint32_t addr) {
    asm volatile("ldmatrix.sync.aligned.m8n8.x4.shared.b16 {%0,%1,%2,%3}, [%4];"
        : "=r"(r[0]), "=r"(r[1]), "=r"(r[2]), "=r"(r[3]) : "r"(addr));
}
__device__ __forceinline__ void ldsm4t(uint32_t* r, uint32_t addr) {
    asm volatile("ldmatrix.sync.aligned.m8n8.x4.trans.shared.b16 {%0,%1,%2,%3}, [%4];"
        : "=r"(r[0]), "=r"(r[1]), "=r"(r[2]), "=r"(r[3]) : "r"(addr));
}
__device__ __forceinline__ void mma16816(float* c, const uint32_t* a, const uint32_t* b) {
    asm volatile(
        "mma.sync.aligned.m16n8k16.row.col.f32.bf16.bf16.f32 "
        "{%0,%1,%2,%3}, {%4,%5,%6,%7}, {%8,%9}, {%0,%1,%2,%3};"
        : "+f"(c[0]), "+f"(c[1]), "+f"(c[2]), "+f"(c[3])
        : "r"(a[0]), "r"(a[1]), "r"(a[2]), "r"(a[3]), "r"(b[0]), "r"(b[1]));
}
// pack 2 floats into bf16x2 hi + residual lo
__device__ __forceinline__ void split2(float a, float b, uint32_t& hi, uint32_t& lo) {
    __nv_bfloat16 ah = __float2bfloat16_rn(a);
    __nv_bfloat16 bh = __float2bfloat16_rn(b);
    float ar = a - __bfloat162float(ah);
    float br = b - __bfloat162float(bh);
    __nv_bfloat16 al = __float2bfloat16_rn(ar);
    __nv_bfloat16 bl = __float2bfloat16_rn(br);
    hi = ((uint32_t)__bfloat16_as_ushort(bh) << 16) | __bfloat16_as_ushort(ah);
    lo = ((uint32_t)__bfloat16_as_ushort(bl) << 16) | __bfloat16_as_ushort(al);
}

// ---------------- tiny utility kernels ----------------
__global__ void k_zeroi(int* p, int n) {
    int i = blockIdx.x * blockDim.x + threadIdx.x;
    if (i < n) p[i] = 0;
}
__global__ void k_zerof(float* p, int n) {
    int i = blockIdx.x * blockDim.x + threadIdx.x;
    if (i < n) p[i] = 0.f;
}
__global__ void k_copyi(const int* __restrict__ a, int* __restrict__ b, int n) {
    int i = blockIdx.x * blockDim.x + threadIdx.x;
    if (i < n) b[i] = a[i];
}

// ---------------- CSR construction ----------------
__global__ void k_count(const int* __restrict__ eu, const int* __restrict__ ei,
                        int* cu, int* ci) {
    int k = blockIdx.x * blockDim.x + threadIdx.x;
    if (k < NEDG) {
        atomicAdd(&ci[ei[k]], 1);
        atomicAdd(&cu[eu[k]], 1);
    }
}

__global__ void k_scan_blk(const int* __restrict__ cnt, int n,
                           int* __restrict__ rp, int* __restrict__ part) {
    __shared__ int ws[32];
    int tid = threadIdx.x;
    int i = blockIdx.x * 1024 + tid;
    int v = (i < n) ? cnt[i] : 0;
    int lane = tid & 31, w = tid >> 5;
    int x = v;
    #pragma unroll
    for (int o = 1; o < 32; o <<= 1) {
        int y = __shfl_up_sync(0xffffffffu, x, o);
        if (lane >= o) x += y;
    }
    if (lane == 31) ws[w] = x;
    __syncthreads();
    if (w == 0) {
        int t = ws[lane];
        #pragma unroll
        for (int o = 1; o < 32; o <<= 1) {
            int y = __shfl_up_sync(0xffffffffu, t, o);
            if (lane >= o) t += y;
        }
        ws[lane] = t;
    }
    __syncthreads();
    int incl = x + (w > 0 ? ws[w - 1] : 0);
    if (i < n) rp[i + 1] = incl;
    if (tid == 1023) part[blockIdx.x] = incl;
}
__global__ void k_scan_part(int* part, int nb) {
    __shared__ int w0sum;
    int tid = threadIdx.x;   // 64
    int v = (tid < nb) ? part[tid] : 0;
    int lane = tid & 31, w = tid >> 5;
    int x = v;
    #pragma unroll
    for (int o = 1; o < 32; o <<= 1) {
        int y = __shfl_up_sync(0xffffffffu, x, o);
        if (lane >= o) x += y;
    }
    if (w == 0 && lane == 31) w0sum = x;
    __syncthreads();
    int incl = x + (w ? w0sum : 0);
    if (tid < nb) part[tid] = incl - v;
}
__global__ void k_scan_add(int* __restrict__ rp, const int* __restrict__ part, int n) {
    int i = blockIdx.x * 1024 + threadIdx.x;
    if (i < n) rp[i + 1] += part[blockIdx.x];
    if (i == 0) rp[0] = 0;
}

__global__ void k_scatter(const int* __restrict__ eu, const int* __restrict__ ei,
                          int* cu, int* ci,
                          int* __restrict__ su, int* __restrict__ si) {
    int k = blockIdx.x * blockDim.x + threadIdx.x;
    if (k < NEDG) {
        int u = eu[k], it = ei[k];
        int p = atomicAdd(&ci[it], 1);
        si[p] = u;
        int q = atomicAdd(&cu[u], 1);
        su[q] = it;
    }
}

// ---------------- weight bf16 split: W[K,N] fp32 -> Bh/Bl[K,N] bf16 ----------------
__global__ void k_splitB(const float* __restrict__ W, __nv_bfloat16* __restrict__ bh,
                         __nv_bfloat16* __restrict__ bl, int total) {
    int id = blockIdx.x * blockDim.x + threadIdx.x;
    if (id >= total) return;
    float v = W[id];
    __nv_bfloat16 h = __float2bfloat16_rn(v);
    bh[id] = h;
    bl[id] = __float2bfloat16_rn(v - __bfloat162float(h));
}

// ---------------- tensor-core GEMM: C[M,N] = A[M,K] @ W[K,N], bf16x3 ----------------
// BM=128, BN=128, BK=32. 8 warps, warp tile 64x32.
// smem: A_hi 128 rows x 80B, A_lo same; B_hi 32 rows x 272B, B_lo same.
#define SA_STR 80
#define SB_STR 272
#define OFF_AH 0
#define OFF_AL 10240
#define OFF_BH 20480
#define OFF_BL (20480 + 8704)
#define SMEM_GEMM (20480 + 2 * 8704)

__global__ void __launch_bounds__(256)
k_mma_gemm(const float* __restrict__ A, const __nv_bfloat16* __restrict__ Bh,
           const __nv_bfloat16* __restrict__ Bl, float* __restrict__ C,
           int M, int K, int N) {
    __shared__ __align__(16) char smem[SMEM_GEMM];
    uint32_t sb = smem_u32(smem);
    int tid = threadIdx.x;
    int wid = tid >> 5, lane = tid & 31;
    int wm = wid & 1, wn = wid >> 1;     // warp tile: rows wm*64, cols wn*32
    int bm = blockIdx.x * 128;
    int bn = blockIdx.y * 128;

    float acc[4][4][4];
    #pragma unroll
    for (int i = 0; i < 4; i++)
        #pragma unroll
        for (int j = 0; j < 4; j++)
            #pragma unroll
            for (int q = 0; q < 4; q++) acc[i][j][q] = 0.f;

    // staging assignments
    int arow = tid >> 1;          // 0..127
    int ahalf = tid & 1;          // 16-float half of the 32-float row
    int garow = bm + arow;
    // B: 512 16B-chunks per (hi|lo); thread handles chunks tid, tid+256 of each
    int nch = K >> 5;

    // prefetch regs
    float4 pa[4];
    uint4 pbh[2], pbl[2];

    // ---- load chunk 0 ----
    {
        const float* ap = A + (size_t)garow * K + ahalf * 16;
        #pragma unroll
        for (int i = 0; i < 4; i++)
            pa[i] = (garow < M) ? *(const float4*)(ap + i * 4)
                                : make_float4(0.f, 0.f, 0.f, 0.f);
        #pragma unroll
        for (int c = 0; c < 2; c++) {
            int ch = tid + c * 256;
            int k = ch >> 4, cc = ch & 15;
            size_t gi = ((size_t)k * N + bn + cc * 8) >> 3;  // uint4 index (8 bf16)
            pbh[c] = ((const uint4*)Bh)[gi];
            pbl[c] = ((const uint4*)Bl)[gi];
        }
    }

    for (int kc = 0; kc < nch; kc++) {
        // ---- stage current regs into smem ----
        {
            uint32_t hi[8], lo[8];
            #pragma unroll
            for (int i = 0; i < 4; i++) {
                split2(pa[i].x, pa[i].y, hi[2 * i], lo[2 * i]);
                split2(pa[i].z, pa[i].w, hi[2 * i + 1], lo[2 * i + 1]);
            }
            char* dst = smem + OFF_AH + arow * SA_STR + ahalf * 32;
            ((uint4*)dst)[0] = make_uint4(hi[0], hi[1], hi[2], hi[3]);
            ((uint4*)dst)[1] = make_uint4(hi[4], hi[5], hi[6], hi[7]);
            char* dstl = smem + OFF_AL + arow * SA_STR + ahalf * 32;
            ((uint4*)dstl)[0] = make_uint4(lo[0], lo[1], lo[2], lo[3]);
            ((uint4*)dstl)[1] = make_uint4(lo[4], lo[5], lo[6], lo[7]);
            #pragma unroll
            for (int c = 0; c < 2; c++) {
                int ch = tid + c * 256;
                int k = ch >> 4, cc = ch & 15;
                *(uint4*)(smem + OFF_BH + k * SB_STR + cc * 16) = pbh[c];
                *(uint4*)(smem + OFF_BL + k * SB_STR + cc * 16) = pbl[c];
            }
        }
        __syncthreads();
        // ---- prefetch next chunk ----
        if (kc + 1 < nch) {
            int k0 = (kc + 1) << 5;
            const float* ap = A + (size_t)garow * K + k0 + ahalf * 16;
            #pragma unroll
            for (int i = 0; i < 4; i++)
                pa[i] = (garow < M) ? *(const float4*)(ap + i * 4)
                                    : make_float4(0.f, 0.f, 0.f, 0.f);
            #pragma unroll
            for (int c = 0; c < 2; c++) {
                int ch = tid + c * 256;
                int k = ch >> 4, cc = ch & 15;
                size_t gi = ((size_t)(k0 + k) * N + bn + cc * 8) >> 3;
                pbh[c] = ((const uint4*)Bh)[gi];
                pbl[c] = ((const uint4*)Bl)[gi];
            }
        }
        // ---- mma on staged tile ----
        #pragma unroll
        for (int s = 0; s < 2; s++) {
            uint32_t Af[4][4], Alf[4][4], Bf[4][2], Blf[4][2];
            #pragma unroll
            for (int mt = 0; mt < 4; mt++) {
                uint32_t ad = sb + OFF_AH +
                              (uint32_t)(wm * 64 + mt * 16 + (lane & 15)) * SA_STR +
                              s * 32 + (lane >> 4) * 16;
                ldsm4(Af[mt], ad);
                ldsm4(Alf[mt], ad + (OFF_AL - OFF_AH));
            }
            #pragma unroll
            for (int np = 0; np < 2; np++) {
                int g = lane >> 3, r = lane & 7;
                int k = s * 16 + (g & 1) * 8 + r;
                int n = wn * 32 + np * 16 + (g >> 1) * 8;
                uint32_t bd = sb + OFF_BH + (uint32_t)k * SB_STR + n * 2;
                uint32_t t[4];
                ldsm4t(t, bd);
                Bf[2 * np][0] = t[0]; Bf[2 * np][1] = t[1];
                Bf[2 * np + 1][0] = t[2]; Bf[2 * np + 1][1] = t[3];
                ldsm4t(t, bd + (OFF_BL - OFF_BH));
                Blf[2 * np][0] = t[0]; Blf[2 * np][1] = t[1];
                Blf[2 * np + 1][0] = t[2]; Blf[2 * np + 1][1] = t[3];
            }
            #pragma unroll
            for (int mt = 0; mt < 4; mt++)
                #pragma unroll
                for (int nt = 0; nt < 4; nt++) {
                    mma16816(acc[mt][nt], Af[mt], Bf[nt]);
                    mma16816(acc[mt][nt], Af[mt], Blf[nt]);
                    mma16816(acc[mt][nt], Alf[mt], Bf[nt]);
                }
        }
        __syncthreads();
    }

    // ---- epilogue ----
    int grp = lane >> 2, tq = lane & 3;
    #pragma unroll
    for (int mt = 0; mt < 4; mt++) {
        int r0 = bm + wm * 64 + mt * 16 + grp;
        int r1 = r0 + 8;
        #pragma unroll
        for (int nt = 0; nt < 4; nt++) {
            int col = bn + wn * 32 + nt * 8 + tq * 2;
            if (r0 < M)
                *(float2*)(C + (size_t)r0 * N + col) =
                    make_float2(acc[mt][nt][0], acc[mt][nt][1]);
            if (r1 < M)
                *(float2*)(C + (size_t)r1 * N + col) =
                    make_float2(acc[mt][nt][2], acc[mt][nt][3]);
        }
    }
}

// ---------------- el[n,h] = per-head dot(hs[n], A0[h]) ----------------
__global__ void k_el(const float* __restrict__ hs, const float* __restrict__ A,
                     float* __restrict__ el, int n, int F) {
    int w = (blockIdx.x * blockDim.x + threadIdx.x) >> 5;
    int lane = threadIdx.x & 31;
    if (w >= n) return;
    int CH = F >> 5;
    const float* row = hs + (size_t)w * F + lane * CH;
    float p = 0.f;
    for (int c = 0; c < CH; c++) p += row[c] * A[lane * CH + c];
    p += __shfl_down_sync(0xffffffffu, p, 4, 8);
    p += __shfl_down_sync(0xffffffffu, p, 2, 8);
    p += __shfl_down_sync(0xffffffffu, p, 1, 8);
    if ((lane & 7) == 0) el[w * 4 + (lane >> 3)] = p;
}

// ---------------- V[k,h] = sum_d W[k, h*dh+d] * A1[h,d] ----------------
__global__ void k_collapseV(const float* __restrict__ W, const float* __restrict__ A,
                            float* __restrict__ V, int fin, int F, int dh) {
    int t = blockIdx.x * blockDim.x + threadIdx.x;
    if (t >= fin * NHEAD) return;
    int k = t >> 2, h = t & 3;
    const float* A1 = A + NHEAD * dh;
    float s = 0.f;
    for (int d = 0; d < dh; d++)
        s += W[(size_t)k * F + h * dh + d] * A1[h * dh + d];
    V[t] = s;
}

// ---------------- er[n,:] = X[n,:] @ V ----------------
__global__ void k_er(const float* __restrict__ X, const float4* __restrict__ V4,
                     float* __restrict__ er, int n, int fin) {
    int w = (blockIdx.x * blockDim.x + threadIdx.x) >> 5;
    int lane = threadIdx.x & 31;
    if (w >= n) return;
    const float* x = X + (size_t)w * fin;
    float a0 = 0.f, a1 = 0.f, a2 = 0.f, a3 = 0.f;
    for (int k = lane; k < fin; k += 32) {
        float xv = x[k];
        float4 v = V4[k];
        a0 += xv * v.x; a1 += xv * v.y; a2 += xv * v.z; a3 += xv * v.w;
    }
    #pragma unroll
    for (int o = 16; o; o >>= 1) {
        a0 += __shfl_xor_sync(0xffffffffu, a0, o);
        a1 += __shfl_xor_sync(0xffffffffu, a1, o);
        a2 += __shfl_xor_sync(0xffffffffu, a2, o);
        a3 += __shfl_xor_sync(0xffffffffu, a3, o);
    }
    if (lane == 0) {
        er[w * 4 + 0] = a0; er[w * 4 + 1] = a1;
        er[w * 4 + 2] = a2; er[w * 4 + 3] = a3;
    }
}

__device__ __forceinline__ float lrelu(float x, float s) { return x > 0.f ? x : s * x; }

// ---------------- segment softmax ----------------
__global__ void k_attn(const int* __restrict__ rp, const int* __restrict__ srcs,
                       const float4* __restrict__ el4, const float4* __restrict__ er4,
                       float4* __restrict__ alpha4, int ndst) {
    int w = (blockIdx.x * blockDim.x + threadIdx.x) >> 5;
    int lane = threadIdx.x & 31;
    if (w >= ndst) return;
    int s0 = rp[w], s1 = rp[w + 1];
    if (s0 == s1) return;
    float4 er = er4[w];
    float m0 = -1e30f, m1 = -1e30f, m2 = -1e30f, m3 = -1e30f;
    for (int j = s0 + lane; j < s1; j += 32) {
        float4 e = el4[srcs[j]];
        m0 = fmaxf(m0, lrelu(e.x + er.x, 0.2f));
        m1 = fmaxf(m1, lrelu(e.y + er.y, 0.2f));
        m2 = fmaxf(m2, lrelu(e.z + er.z, 0.2f));
        m3 = fmaxf(m3, lrelu(e.w + er.w, 0.2f));
    }
    #pragma unroll
    for (int o = 16; o; o >>= 1) {
        m0 = fmaxf(m0, __shfl_xor_sync(0xffffffffu, m0, o));
        m1 = fmaxf(m1, __shfl_xor_sync(0xffffffffu, m1, o));
        m2 = fmaxf(m2, __shfl_xor_sync(0xffffffffu, m2, o));
        m3 = fmaxf(m3, __shfl_xor_sync(0xffffffffu, m3, o));
    }
    float z0 = 0.f, z1 = 0.f, z2 = 0.f, z3 = 0.f;
    for (int j = s0 + lane; j < s1; j += 32) {
        float4 e = el4[srcs[j]];
        z0 += expf(lrelu(e.x + er.x, 0.2f) - m0);
        z1 += expf(lrelu(e.y + er.y, 0.2f) - m1);
        z2 += expf(lrelu(e.z + er.z, 0.2f) - m2);
        z3 += expf(lrelu(e.w + er.w, 0.2f) - m3);
    }
    #pragma unroll
    for (int o = 16; o; o >>= 1) {
        z0 += __shfl_xor_sync(0xffffffffu, z0, o);
        z1 += __shfl_xor_sync(0xffffffffu, z1, o);
        z2 += __shfl_xor_sync(0xffffffffu, z2, o);
        z3 += __shfl_xor_sync(0xffffffffu, z3, o);
    }
    float i0 = 1.f / z0, i1 = 1.f / z1, i2 = 1.f / z2, i3 = 1.f / z3;
    for (int j = s0 + lane; j < s1; j += 32) {
        float4 e = el4[srcs[j]];
        float4 a;
        a.x = expf(lrelu(e.x + er.x, 0.2f) - m0) * i0;
        a.y = expf(lrelu(e.y + er.y, 0.2f) - m1) * i1;
        a.z = expf(lrelu(e.z + er.z, 0.2f) - m2) * i2;
        a.w = expf(lrelu(e.w + er.w, 0.2f) - m3) * i3;
        alpha4[j] = a;
    }
}

// ---------------- aggregation ----------------
__global__ void k_aggr256(const int* __restrict__ rp, const int* __restrict__ srcs,
                          const float4* __restrict__ alpha4, const float* __restrict__ hs,
                          float* __restrict__ out, int ndst) {
    int w = (blockIdx.x * blockDim.x + threadIdx.x) >> 5;
    int lane = threadIdx.x & 31;
    if (w >= ndst) return;
    int s0 = rp[w], s1 = rp[w + 1];
    float4 acc0 = make_float4(0.f, 0.f, 0.f, 0.f);
    float4 acc1 = make_float4(0.f, 0.f, 0.f, 0.f);
    for (int j = s0; j < s1; j++) {
        int s = srcs[j];
        float4 al = alpha4[j];
        float a0 = (lane < 16) ? al.x : al.y;
        float a1 = (lane < 16) ? al.z : al.w;
        const float4* row = (const float4*)(hs + (size_t)s * 256);
        float4 v0 = row[lane];
        float4 v1 = row[lane + 32];
        acc0.x += a0 * v0.x; acc0.y += a0 * v0.y; acc0.z += a0 * v0.z; acc0.w += a0 * v0.w;
        acc1.x += a1 * v1.x; acc1.y += a1 * v1.y; acc1.z += a1 * v1.z; acc1.w += a1 * v1.w;
    }
    float4* o = (float4*)(out + (size_t)w * 256);
    o[lane] = acc0;
    o[lane + 32] = acc1;
}

__global__ void k_aggr128(const int* __restrict__ rp, const int* __restrict__ srcs,
                          const float4* __restrict__ alpha4, const float* __restrict__ hs,
                          float* __restrict__ out, int ndst) {
    int w = (blockIdx.x * blockDim.x + threadIdx.x) >> 5;
    int lane = threadIdx.x & 31;
    if (w >= ndst) return;
    int s0 = rp[w], s1 = rp[w + 1];
    float4 acc = make_float4(0.f, 0.f, 0.f, 0.f);
    for (int j = s0; j < s1; j++) {
        int s = srcs[j];
        float4 al = alpha4[j];
        float a = (lane & 8) ? ((lane & 16) ? al.w : al.y)
                             : ((lane & 16) ? al.z : al.x);
        const float4* row = (const float4*)(hs + (size_t)s * 128);
        float4 v = row[lane];
        acc.x += a * v.x; acc.y += a * v.y; acc.z += a * v.z; acc.w += a * v.w;
    }
    ((float4*)(out + (size_t)w * 128))[lane] = acc;
}

// ---------------- BatchNorm ----------------
__global__ void k_bnstats(const float* __restrict__ x, float* __restrict__ stats, int n) {
    int c = threadIdx.x;
    float s = 0.f, q = 0.f;
    for (int r = blockIdx.x; r < n; r += gridDim.x) {
        float v = x[(size_t)r * 256 + c];
        s += v;
        q += v * v;
    }
    atomicAdd(&stats[c], s);
    atomicAdd(&stats[256 + c], q);
}

__global__ void k_bnapply(const float* __restrict__ x, float* __restrict__ y,
                          const float* __restrict__ bn, const float* __restrict__ stats,
                          int L, int n, int use_tanh) {
    int c = threadIdx.x;
    float mu = stats[c] / (float)n;
    float var = stats[256 + c] / (float)n - mu * mu;
    float gamma = bn[(L * 2 + 0) * 256 + c];
    float beta  = bn[(L * 2 + 1) * 256 + c];
    float sc = gamma * rsqrtf(var + 1e-5f);
    float sh = beta - mu * sc;
    for (int r = blockIdx.x; r < n; r += gridDim.x) {
        size_t idx = (size_t)r * 256 + c;
        float v = sc * x[idx] + sh;
        y[idx] = use_tanh ? tanhf(v) : (v > 0.f ? v : 0.01f * v);
    }
}

// ---------------- host orchestration ----------------
static inline int wgrid(int nwarp) { return (nwarp * 32 + 255) / 256; }

struct Ptrs {
    float *hu, *hi, *hsu, *hsi, *nu, *ni;
    float *el_u, *el_i, *er_u, *er_i, *alpha_i, *alpha_u, *V, *stats;
    __nv_bfloat16 *Bh, *Bl;
    int *rp_i, *rp_u, *srcs_i, *srcs_u, *cur_i, *cur_u, *part;
};

static void get_ptrs(Ptrs& p) {
    cudaGetSymbolAddress((void**)&p.hu, g_hu);
    cudaGetSymbolAddress((void**)&p.hi, g_hi);
    cudaGetSymbolAddress((void**)&p.hsu, g_hsu);
    cudaGetSymbolAddress((void**)&p.hsi, g_hsi);
    cudaGetSymbolAddress((void**)&p.nu, g_nu);
    cudaGetSymbolAddress((void**)&p.ni, g_ni);
    cudaGetSymbolAddress((void**)&p.el_u, g_el_u);
    cudaGetSymbolAddress((void**)&p.el_i, g_el_i);
    cudaGetSymbolAddress((void**)&p.er_u, g_er_u);
    cudaGetSymbolAddress((void**)&p.er_i, g_er_i);
    cudaGetSymbolAddress((void**)&p.alpha_i, g_alpha_i);
    cudaGetSymbolAddress((void**)&p.alpha_u, g_alpha_u);
    cudaGetSymbolAddress((void**)&p.V, g_V);
    cudaGetSymbolAddress((void**)&p.stats, g_stats);
    cudaGetSymbolAddress((void**)&p.Bh, g_Bh);
    cudaGetSymbolAddress((void**)&p.Bl, g_Bl);
    cudaGetSymbolAddress((void**)&p.rp_i, g_rp_i);
    cudaGetSymbolAddress((void**)&p.rp_u, g_rp_u);
    cudaGetSymbolAddress((void**)&p.srcs_i, g_srcs_i);
    cudaGetSymbolAddress((void**)&p.srcs_u, g_srcs_u);
    cudaGetSymbolAddress((void**)&p.cur_i, g_cur_i);
    cudaGetSymbolAddress((void**)&p.cur_u, g_cur_u);
    cudaGetSymbolAddress((void**)&p.part, g_part);
}

static void tcgemm(const Ptrs& p, const float* A, const float* W, float* C,
                   int M, int K, int N) {
    k_splitB<<<(K * N + 255) / 256, 256>>>(W, p.Bh, p.Bl, K * N);
    dim3 g((M + 127) / 128, N / 128);
    k_mma_gemm<<<g, 256>>>(A, p.Bh, p.Bl, C, M, K, N);
}

static void scan(const int* cnt, int n, int* rp, int* part) {
    int nb = (n + 1023) / 1024;
    k_scan_blk<<<nb, 1024>>>(cnt, n, rp, part);
    k_scan_part<<<1, 64>>>(part, nb);
    k_scan_add<<<nb, 1024>>>(rp, part, n);
}

static void relation_pass(const Ptrs& p, const float* cu, const float* ci,
                          const float* Wui, const float* Aui,
                          const float* Wiu, const float* Aiu,
                          int fin, int F, int dh,
                          float* outu, float* outi) {
    tcgemm(p, cu, Wui, p.hsu, NUSR, fin, F);
    tcgemm(p, ci, Wiu, p.hsi, NITM, fin, F);
    k_el<<<wgrid(NUSR), 256>>>(p.hsu, Aui, p.el_u, NUSR, F);
    k_el<<<wgrid(NITM), 256>>>(p.hsi, Aiu, p.el_i, NITM, F);
    k_collapseV<<<(fin * 4 + 255) / 256, 256>>>(Wui, Aui, p.V, fin, F, dh);
    k_er<<<wgrid(NITM), 256>>>(ci, (const float4*)p.V, p.er_i, NITM, fin);
    k_collapseV<<<(fin * 4 + 255) / 256, 256>>>(Wiu, Aiu, p.V, fin, F, dh);
    k_er<<<wgrid(NUSR), 256>>>(cu, (const float4*)p.V, p.er_u, NUSR, fin);
    k_attn<<<wgrid(NITM), 256>>>(p.rp_i, p.srcs_i, (const float4*)p.el_u,
                                 (const float4*)p.er_i, (float4*)p.alpha_i, NITM);
    k_attn<<<wgrid(NUSR), 256>>>(p.rp_u, p.srcs_u, (const float4*)p.el_i,
                                 (const float4*)p.er_u, (float4*)p.alpha_u, NUSR);
    if (F == 256) {
        k_aggr256<<<wgrid(NITM), 256>>>(p.rp_i, p.srcs_i, (const float4*)p.alpha_i,
                                        p.hsu, outi, NITM);
        k_aggr256<<<wgrid(NUSR), 256>>>(p.rp_u, p.srcs_u, (const float4*)p.alpha_u,
                                        p.hsi, outu, NUSR);
    } else {
        k_aggr128<<<wgrid(NITM), 256>>>(p.rp_i, p.srcs_i, (const float4*)p.alpha_i,
                                        p.hsu, outi, NITM);
        k_aggr128<<<wgrid(NUSR), 256>>>(p.rp_u, p.srcs_u, (const float4*)p.alpha_u,
                                        p.hsi, outu, NUSR);
    }
}

extern "C" void kernel_launch(void* const* d_in, const int* in_sizes, int n_in,
                              void* d_out, int out_size) {
    Ptrs p;
    get_ptrs(p);

    const float* x_user = (const float*)d_in[0];
    const float* x_item = (const float*)d_in[1];
    const int*   eu     = (const int*)d_in[2];
    const int*   ei     = (const int*)d_in[3];

    bool dictOrder = (in_sizes[5] < 10000);
    const float *Wui[4], *Aui[4], *Wiu[4], *Aiu[4];
    for (int L = 0; L < 4; L++) {
        if (dictOrder) {
            Wui[L] = (const float*)d_in[4 + L * 4 + 0];
            Aui[L] = (const float*)d_in[4 + L * 4 + 1];
            Wiu[L] = (const float*)d_in[4 + L * 4 + 2];
            Aiu[L] = (const float*)d_in[4 + L * 4 + 3];
        } else {
            Wui[L] = (const float*)d_in[4 + L * 4 + 0];
            Wiu[L] = (const float*)d_in[4 + L * 4 + 1];
            Aui[L] = (const float*)d_in[4 + L * 4 + 2];
            Aiu[L] = (const float*)d_in[4 + L * 4 + 3];
        }
    }
    const float* bn_u = (const float*)d_in[20];
    const float* bn_i = (const float*)d_in[21];
    float* out = (float*)d_out;

    // ---- CSR build ----
    k_zeroi<<<(NUSR + 255) / 256, 256>>>(p.cur_u, NUSR);
    k_zeroi<<<(NITM + 255) / 256, 256>>>(p.cur_i, NITM);
    k_count<<<(NEDG + 255) / 256, 256>>>(eu, ei, p.cur_u, p.cur_i);
    scan(p.cur_i, NITM, p.rp_i, p.part);
    scan(p.cur_u, NUSR, p.rp_u, p.part);
    k_copyi<<<(NITM + 255) / 256, 256>>>(p.rp_i, p.cur_i, NITM);
    k_copyi<<<(NUSR + 255) / 256, 256>>>(p.rp_u, p.cur_u, NUSR);
    k_scatter<<<(NEDG + 255) / 256, 256>>>(eu, ei, p.cur_u, p.cur_i, p.srcs_u, p.srcs_i);

    // ---- hidden layers 0..2 ----
    const float* cu = x_user;
    const float* ci = x_item;
    int fin = FIN0;
    for (int L = 0; L < 3; L++) {
        relation_pass(p, cu, ci, Wui[L], Aui[L], Wiu[L], Aiu[L],
                      fin, 256, 64, p.nu, p.ni);
        int tanh_act = (L == 2) ? 1 : 0;
        k_zerof<<<2, 256>>>(p.stats, 512);
        k_bnstats<<<256, 256>>>(p.nu, p.stats, NUSR);
        k_bnapply<<<256, 256>>>(p.nu, p.hu, bn_u, p.stats, L, NUSR, tanh_act);
        k_zerof<<<2, 256>>>(p.stats, 512);
        k_bnstats<<<256, 256>>>(p.ni, p.stats, NITM);
        k_bnapply<<<256, 256>>>(p.ni, p.hi, bn_i, p.stats, L, NITM, tanh_act);
        cu = p.hu;
        ci = p.hi;
        fin = FHID;
    }

    // ---- output layer 3 ----
    relation_pass(p, cu, ci, Wui[3], Aui[3], Wiu[3], Aiu[3],
                  256, 128, 32,
                  out, out + (size_t)NUSR * 128);
    (void)n_in; (void)out_size;
}

// round 4
// speedup vs baseline: 1.3275x; 1.0194x over previous
#include <cuda_runtime.h>
#include <cuda_bf16.h>
#include <math.h>
#include <stddef.h>
#include <stdint.h>

// ---------------- problem constants ----------------
#define NUSR 50000
#define NITM 20000
#define NEDG 400000
#define FIN0 128
#define FHID 256
#define NHEAD 4

// ---------------- device scratch (no allocs allowed) ----------------
__device__ float g_hu [(size_t)NUSR * FHID];
__device__ float g_hi [(size_t)NITM * FHID];
__device__ float g_hsu[(size_t)NUSR * FHID];
__device__ float g_hsi[(size_t)NITM * FHID];
__device__ float g_nu [(size_t)NUSR * FHID];
__device__ float g_ni [(size_t)NITM * FHID];
__device__ float g_el_u[NUSR * 4];
__device__ float g_el_i[NITM * 4];
__device__ float g_er_u[NUSR * 4];
__device__ float g_er_i[NITM * 4];
__device__ int   g_rp_i[NITM + 1];
__device__ int   g_rp_u[NUSR + 1];
__device__ int   g_srcs_i[NEDG];
__device__ int   g_srcs_u[NEDG];
__device__ int   g_cur_i[NITM];
__device__ int   g_cur_u[NUSR];
__device__ float g_V[FHID * NHEAD];
__device__ float g_stats[2 * FHID];
__device__ int   g_part[64];
__device__ __nv_bfloat16 g_Bh[FHID * FHID];
__device__ __nv_bfloat16 g_Bl[FHID * FHID];
__device__ __nv_bfloat16 g_Auh[(size_t)NUSR * FHID];  // user activations hi
__device__ __nv_bfloat16 g_Aul[(size_t)NUSR * FHID];  // user activations lo
__device__ __nv_bfloat16 g_Aih[(size_t)NITM * FHID];  // item activations hi
__device__ __nv_bfloat16 g_Ail[(size_t)NITM * FHID];  // item activations lo

// ---------------- PTX helpers (baseline features only) ----------------
__device__ __forceinline__ uint32_t smem_u32(const void* p) {
    uint32_t a;
    asm("{ .reg .u64 t; cvta.to.shared.u64 t, %1; cvt.u32.u64 %0, t; }"
        : "=r"(a) : "l"(p));
    return a;
}
__device__ __forceinline__ void ldsm4(uint32_t* r, uint32_t addr) {
    asm volatile("ldmatrix.sync.aligned.m8n8.x4.shared.b16 {%0,%1,%2,%3}, [%4];"
        : "=r"(r[0]), "=r"(r[1]), "=r"(r[2]), "=r"(r[3]) : "r"(addr));
}
__device__ __forceinline__ void ldsm4t(uint32_t* r, uint32_t addr) {
    asm volatile("ldmatrix.sync.aligned.m8n8.x4.trans.shared.b16 {%0,%1,%2,%3}, [%4];"
        : "=r"(r[0]), "=r"(r[1]), "=r"(r[2]), "=r"(r[3]) : "r"(addr));
}
__device__ __forceinline__ void mma16816(float* c, const uint32_t* a,
                                         uint32_t b0, uint32_t b1) {
    asm volatile(
        "mma.sync.aligned.m16n8k16.row.col.f32.bf16.bf16.f32 "
        "{%0,%1,%2,%3}, {%4,%5,%6,%7}, {%8,%9}, {%0,%1,%2,%3};"
        : "+f"(c[0]), "+f"(c[1]), "+f"(c[2]), "+f"(c[3])
        : "r"(a[0]), "r"(a[1]), "r"(a[2]), "r"(a[3]), "r"(b0), "r"(b1));
}
#define CPA16(dst, src) \
    asm volatile("cp.async.cg.shared.global [%0], [%1], 16;" \
                 :: "r"(dst), "l"(src))
#define CP_COMMIT() asm volatile("cp.async.commit_group;")
#define CP_WAIT1()  asm volatile("cp.async.wait_group 1;" ::: "memory")
#define CP_WAIT0()  asm volatile("cp.async.wait_group 0;" ::: "memory")

// ---------------- tiny utility kernels ----------------
__global__ void k_zeroi(int* p, int n) {
    int i = blockIdx.x * blockDim.x + threadIdx.x;
    if (i < n) p[i] = 0;
}
__global__ void k_zerof(float* p, int n) {
    int i = blockIdx.x * blockDim.x + threadIdx.x;
    if (i < n) p[i] = 0.f;
}
__global__ void k_copyi(const int* __restrict__ a, int* __restrict__ b, int n) {
    int i = blockIdx.x * blockDim.x + threadIdx.x;
    if (i < n) b[i] = a[i];
}

// ---------------- CSR construction ----------------
__global__ void k_count(const int* __restrict__ eu, const int* __restrict__ ei,
                        int* cu, int* ci) {
    int k = blockIdx.x * blockDim.x + threadIdx.x;
    if (k < NEDG) {
        atomicAdd(&ci[ei[k]], 1);
        atomicAdd(&cu[eu[k]], 1);
    }
}
__global__ void k_scan_blk(const int* __restrict__ cnt, int n,
                           int* __restrict__ rp, int* __restrict__ part) {
    __shared__ int ws[32];
    int tid = threadIdx.x;
    int i = blockIdx.x * 1024 + tid;
    int v = (i < n) ? cnt[i] : 0;
    int lane = tid & 31, w = tid >> 5;
    int x = v;
    #pragma unroll
    for (int o = 1; o < 32; o <<= 1) {
        int y = __shfl_up_sync(0xffffffffu, x, o);
        if (lane >= o) x += y;
    }
    if (lane == 31) ws[w] = x;
    __syncthreads();
    if (w == 0) {
        int t = ws[lane];
        #pragma unroll
        for (int o = 1; o < 32; o <<= 1) {
            int y = __shfl_up_sync(0xffffffffu, t, o);
            if (lane >= o) t += y;
        }
        ws[lane] = t;
    }
    __syncthreads();
    int incl = x + (w > 0 ? ws[w - 1] : 0);
    if (i < n) rp[i + 1] = incl;
    if (tid == 1023) part[blockIdx.x] = incl;
}
__global__ void k_scan_part(int* part, int nb) {
    __shared__ int w0sum;
    int tid = threadIdx.x;
    int v = (tid < nb) ? part[tid] : 0;
    int lane = tid & 31, w = tid >> 5;
    int x = v;
    #pragma unroll
    for (int o = 1; o < 32; o <<= 1) {
        int y = __shfl_up_sync(0xffffffffu, x, o);
        if (lane >= o) x += y;
    }
    if (w == 0 && lane == 31) w0sum = x;
    __syncthreads();
    int incl = x + (w ? w0sum : 0);
    if (tid < nb) part[tid] = incl - v;
}
__global__ void k_scan_add(int* __restrict__ rp, const int* __restrict__ part, int n) {
    int i = blockIdx.x * 1024 + threadIdx.x;
    if (i < n) rp[i + 1] += part[blockIdx.x];
    if (i == 0) rp[0] = 0;
}
__global__ void k_scatter(const int* __restrict__ eu, const int* __restrict__ ei,
                          int* cu, int* ci,
                          int* __restrict__ su, int* __restrict__ si) {
    int k = blockIdx.x * blockDim.x + threadIdx.x;
    if (k < NEDG) {
        int u = eu[k], it = ei[k];
        int p = atomicAdd(&ci[it], 1);
        si[p] = u;
        int q = atomicAdd(&cu[u], 1);
        su[q] = it;
    }
}

// ---------------- elementwise fp32 -> bf16 hi/lo split ----------------
__global__ void k_split(const float* __restrict__ X, __nv_bfloat16* __restrict__ xh,
                        __nv_bfloat16* __restrict__ xl, int total) {
    int id = blockIdx.x * blockDim.x + threadIdx.x;
    if (id >= total) return;
    float v = X[id];
    __nv_bfloat16 h = __float2bfloat16_rn(v);
    xh[id] = h;
    xl[id] = __float2bfloat16_rn(v - __bfloat162float(h));
}

// ---------------- tensor-core GEMM + fused el epilogue ----------------
// C[M,BN] = A[M,K] @ W[K,BN] via bf16x3 (Ah Bh + Ah Bl + Al Bh).
// el[r,h] = sum_{n in head h} attA[n] * C[r,n] fused in epilogue.
// BM=128, BN=N (256 or 128), BK=32, double-buffered cp.async.
template <int BN, int DH>
__global__ void __launch_bounds__((BN == 256) ? 512 : 256, 1)
k_mma_gemm(const __nv_bfloat16* __restrict__ Ah, const __nv_bfloat16* __restrict__ Al,
           const __nv_bfloat16* __restrict__ Bh, const __nv_bfloat16* __restrict__ Bl,
           const float* __restrict__ attA,
           float* __restrict__ C, float* __restrict__ el, int M, int K) {
    constexpr int NT = (BN == 256) ? 512 : 256;
    constexpr int SBSTR = BN * 2 + 16;
    constexpr int ASZ = 128 * 80;          // one half (hi or lo) of A stage
    constexpr int BOFF = 2 * ASZ;
    constexpr int BSZ = 32 * SBSTR;
    constexpr int STAGE = BOFF + 2 * BSZ;
    constexpr int NBC = 32 * (BN / 8);     // B 16B-chunks per half

    extern __shared__ char smem[];
    uint32_t sb = smem_u32(smem);
    int tid = threadIdx.x;
    int wid = tid >> 5, lane = tid & 31;
    int wm = wid & 3, wn = wid >> 2;       // warp tile rows wm*32, cols wn*64
    int bm = blockIdx.x * 128;

    float acc[2][8][4];
    #pragma unroll
    for (int i = 0; i < 2; i++)
        #pragma unroll
        for (int j = 0; j < 8; j++)
            #pragma unroll
            for (int q = 0; q < 4; q++) acc[i][j][q] = 0.f;

    int nch = K >> 5;

    auto load_stage = [&](int st, int kc) {
        uint32_t sbase = sb + st * STAGE;
        int k0 = kc << 5;
        #pragma unroll
        for (int c = tid; c < 512; c += NT) {
            int row = c >> 2, q = c & 3;
            int gr = bm + row;
            gr = gr < M ? gr : M - 1;
            size_t gi = (size_t)gr * K + k0 + q * 8;
            uint32_t d = sbase + row * 80 + q * 16;
            CPA16(d, Ah + gi);
            CPA16(d + ASZ, Al + gi);
        }
        #pragma unroll
        for (int c = tid; c < NBC; c += NT) {
            int k = c / (BN / 8), seg = c % (BN / 8);
            size_t gi = (size_t)(k0 + k) * BN + seg * 8;
            uint32_t d = sbase + BOFF + k * SBSTR + seg * 16;
            CPA16(d, Bh + gi);
            CPA16(d + BSZ, Bl + gi);
        }
        CP_COMMIT();
    };

    load_stage(0, 0);
    for (int kc = 0; kc < nch; kc++) {
        int cur = kc & 1;
        if (kc + 1 < nch) {
            load_stage(1 - cur, kc + 1);
            CP_WAIT1();
        } else {
            CP_WAIT0();
        }
        __syncthreads();
        uint32_t abase = sb + cur * STAGE;
        #pragma unroll
        for (int s = 0; s < 2; s++) {
            uint32_t Af[2][4], Alf[2][4];
            #pragma unroll
            for (int mt = 0; mt < 2; mt++) {
                uint32_t ad = abase +
                    (uint32_t)(wm * 32 + mt * 16 + (lane & 15)) * 80 +
                    s * 32 + (lane >> 4) * 16;
                ldsm4(Af[mt], ad);
                ldsm4(Alf[mt], ad + ASZ);
            }
            #pragma unroll
            for (int np = 0; np < 4; np++) {
                int g = lane >> 3, r = lane & 7;
                int kk = s * 16 + (g & 1) * 8 + r;
                int nn = wn * 64 + np * 16 + (g >> 1) * 8;
                uint32_t bd = abase + BOFF + (uint32_t)kk * SBSTR + nn * 2;
                uint32_t bh4[4], bl4[4];
                ldsm4t(bh4, bd);
                ldsm4t(bl4, bd + BSZ);
                #pragma unroll
                for (int mt = 0; mt < 2; mt++)
                    #pragma unroll
                    for (int sub = 0; sub < 2; sub++) {
                        float* a = acc[mt][np * 2 + sub];
                        mma16816(a, Af[mt], bh4[2 * sub], bh4[2 * sub + 1]);
                        mma16816(a, Af[mt], bl4[2 * sub], bl4[2 * sub + 1]);
                        mma16816(a, Alf[mt], bh4[2 * sub], bh4[2 * sub + 1]);
                    }
            }
        }
        __syncthreads();
    }

    // ---- epilogue: C write + fused el ----
    constexpr int HPW = 64 / DH;   // heads per warp tile
    int grp = lane >> 2, tq = lane & 3;
    #pragma unroll
    for (int mt = 0; mt < 2; mt++) {
        int r0 = bm + wm * 32 + mt * 16 + grp;
        int r1 = r0 + 8;
        #pragma unroll
        for (int nt = 0; nt < 8; nt++) {
            int col = wn * 64 + nt * 8 + tq * 2;
            if (r0 < M)
                *(float2*)(C + (size_t)r0 * BN + col) =
                    make_float2(acc[mt][nt][0], acc[mt][nt][1]);
            if (r1 < M)
                *(float2*)(C + (size_t)r1 * BN + col) =
                    make_float2(acc[mt][nt][2], acc[mt][nt][3]);
        }
        float s0[HPW], s1[HPW];
        #pragma unroll
        for (int p = 0; p < HPW; p++) { s0[p] = 0.f; s1[p] = 0.f; }
        #pragma unroll
        for (int nt = 0; nt < 8; nt++) {
            int part = (nt * 8) / DH;
            int col = wn * 64 + nt * 8 + tq * 2;
            float c0 = attA[col], c1 = attA[col + 1];
            s0[part] += c0 * acc[mt][nt][0] + c1 * acc[mt][nt][1];
            s1[part] += c0 * acc[mt][nt][2] + c1 * acc[mt][nt][3];
        }
        #pragma unroll
        for (int p = 0; p < HPW; p++) {
            s0[p] += __shfl_xor_sync(0xffffffffu, s0[p], 1);
            s0[p] += __shfl_xor_sync(0xffffffffu, s0[p], 2);
            s1[p] += __shfl_xor_sync(0xffffffffu, s1[p], 1);
            s1[p] += __shfl_xor_sync(0xffffffffu, s1[p], 2);
            if (tq == 0) {
                int h = wn * HPW + p;
                if (r0 < M) el[r0 * 4 + h] = s0[p];
                if (r1 < M) el[r1 * 4 + h] = s1[p];
            }
        }
    }
}

// ---------------- V[k,h] = sum_d W[k, h*dh+d] * A1[h,d] ----------------
__global__ void k_collapseV(const float* __restrict__ W, const float* __restrict__ A,
                            float* __restrict__ V, int fin, int F, int dh) {
    int t = blockIdx.x * blockDim.x + threadIdx.x;
    if (t >= fin * NHEAD) return;
    int k = t >> 2, h = t & 3;
    const float* A1 = A + NHEAD * dh;
    float s = 0.f;
    for (int d = 0; d < dh; d++)
        s += W[(size_t)k * F + h * dh + d] * A1[h * dh + d];
    V[t] = s;
}

// ---------------- er[n,:] = X[n,:] @ V ----------------
__global__ void k_er(const float* __restrict__ X, const float4* __restrict__ V4,
                     float* __restrict__ er, int n, int fin) {
    int w = (blockIdx.x * blockDim.x + threadIdx.x) >> 5;
    int lane = threadIdx.x & 31;
    if (w >= n) return;
    const float* x = X + (size_t)w * fin;
    float a0 = 0.f, a1 = 0.f, a2 = 0.f, a3 = 0.f;
    for (int k = lane; k < fin; k += 32) {
        float xv = x[k];
        float4 v = V4[k];
        a0 += xv * v.x; a1 += xv * v.y; a2 += xv * v.z; a3 += xv * v.w;
    }
    #pragma unroll
    for (int o = 16; o; o >>= 1) {
        a0 += __shfl_xor_sync(0xffffffffu, a0, o);
        a1 += __shfl_xor_sync(0xffffffffu, a1, o);
        a2 += __shfl_xor_sync(0xffffffffu, a2, o);
        a3 += __shfl_xor_sync(0xffffffffu, a3, o);
    }
    if (lane == 0) {
        er[w * 4 + 0] = a0; er[w * 4 + 1] = a1;
        er[w * 4 + 2] = a2; er[w * 4 + 3] = a3;
    }
}

__device__ __forceinline__ float lrelu(float x, float s) { return x > 0.f ? x : s * x; }

// ---------------- fused segment softmax + aggregation, F=256 ----------------
__global__ void k_edge256(const int* __restrict__ rp, const int* __restrict__ srcs,
                          const float4* __restrict__ el4, const float4* __restrict__ er4,
                          const float* __restrict__ hs, float* __restrict__ out,
                          int ndst) {
    int w = (blockIdx.x * blockDim.x + threadIdx.x) >> 5;
    int lane = threadIdx.x & 31;
    if (w >= ndst) return;
    int s0 = rp[w], s1 = rp[w + 1];
    float4* o = (float4*)(out + (size_t)w * 256);
    if (s0 == s1) {
        float4 z = make_float4(0.f, 0.f, 0.f, 0.f);
        o[lane] = z;
        o[lane + 32] = z;
        return;
    }
    float4 er = er4[w];
    float m0 = -1e30f, m1 = -1e30f, m2 = -1e30f, m3 = -1e30f;
    for (int j = s0 + lane; j < s1; j += 32) {
        float4 e = el4[srcs[j]];
        m0 = fmaxf(m0, lrelu(e.x + er.x, 0.2f));
        m1 = fmaxf(m1, lrelu(e.y + er.y, 0.2f));
        m2 = fmaxf(m2, lrelu(e.z + er.z, 0.2f));
        m3 = fmaxf(m3, lrelu(e.w + er.w, 0.2f));
    }
    #pragma unroll
    for (int t = 16; t; t >>= 1) {
        m0 = fmaxf(m0, __shfl_xor_sync(0xffffffffu, m0, t));
        m1 = fmaxf(m1, __shfl_xor_sync(0xffffffffu, m1, t));
        m2 = fmaxf(m2, __shfl_xor_sync(0xffffffffu, m2, t));
        m3 = fmaxf(m3, __shfl_xor_sync(0xffffffffu, m3, t));
    }
    float z0 = 0.f, z1 = 0.f, z2 = 0.f, z3 = 0.f;
    for (int j = s0 + lane; j < s1; j += 32) {
        float4 e = el4[srcs[j]];
        z0 += expf(lrelu(e.x + er.x, 0.2f) - m0);
        z1 += expf(lrelu(e.y + er.y, 0.2f) - m1);
        z2 += expf(lrelu(e.z + er.z, 0.2f) - m2);
        z3 += expf(lrelu(e.w + er.w, 0.2f) - m3);
    }
    #pragma unroll
    for (int t = 16; t; t >>= 1) {
        z0 += __shfl_xor_sync(0xffffffffu, z0, t);
        z1 += __shfl_xor_sync(0xffffffffu, z1, t);
        z2 += __shfl_xor_sync(0xffffffffu, z2, t);
        z3 += __shfl_xor_sync(0xffffffffu, z3, t);
    }
    bool loHalf = lane < 16;
    float mA = loHalf ? m0 : m1, mB = loHalf ? m2 : m3;
    float iA = 1.f / (loHalf ? z0 : z1), iB = 1.f / (loHalf ? z2 : z3);
    float erA = loHalf ? er.x : er.y, erB = loHalf ? er.z : er.w;

    float4 acc0 = make_float4(0.f, 0.f, 0.f, 0.f);
    float4 acc1 = make_float4(0.f, 0.f, 0.f, 0.f);
    for (int j = s0; j < s1; j++) {
        int s = srcs[j];
        float4 e = el4[s];
        float eA = loHalf ? e.x : e.y, eB = loHalf ? e.z : e.w;
        float a0 = expf(lrelu(eA + erA, 0.2f) - mA) * iA;
        float a1 = expf(lrelu(eB + erB, 0.2f) - mB) * iB;
        const float4* row = (const float4*)(hs + (size_t)s * 256);
        float4 v0 = row[lane];
        float4 v1 = row[lane + 32];
        acc0.x += a0 * v0.x; acc0.y += a0 * v0.y; acc0.z += a0 * v0.z; acc0.w += a0 * v0.w;
        acc1.x += a1 * v1.x; acc1.y += a1 * v1.y; acc1.z += a1 * v1.z; acc1.w += a1 * v1.w;
    }
    o[lane] = acc0;
    o[lane + 32] = acc1;
}

// ---------------- fused segment softmax + aggregation, F=128 (dh=32) --------
__global__ void k_edge128(const int* __restrict__ rp, const int* __restrict__ srcs,
                          const float4* __restrict__ el4, const float4* __restrict__ er4,
                          const float* __restrict__ hs, float* __restrict__ out,
                          int ndst) {
    int w = (blockIdx.x * blockDim.x + threadIdx.x) >> 5;
    int lane = threadIdx.x & 31;
    if (w >= ndst) return;
    int s0 = rp[w], s1 = rp[w + 1];
    float4* o = (float4*)(out + (size_t)w * 128);
    if (s0 == s1) {
        o[lane] = make_float4(0.f, 0.f, 0.f, 0.f);
        return;
    }
    float4 er = er4[w];
    float m0 = -1e30f, m1 = -1e30f, m2 = -1e30f, m3 = -1e30f;
    for (int j = s0 + lane; j < s1; j += 32) {
        float4 e = el4[srcs[j]];
        m0 = fmaxf(m0, lrelu(e.x + er.x, 0.2f));
        m1 = fmaxf(m1, lrelu(e.y + er.y, 0.2f));
        m2 = fmaxf(m2, lrelu(e.z + er.z, 0.2f));
        m3 = fmaxf(m3, lrelu(e.w + er.w, 0.2f));
    }
    #pragma unroll
    for (int t = 16; t; t >>= 1) {
        m0 = fmaxf(m0, __shfl_xor_sync(0xffffffffu, m0, t));
        m1 = fmaxf(m1, __shfl_xor_sync(0xffffffffu, m1, t));
        m2 = fmaxf(m2, __shfl_xor_sync(0xffffffffu, m2, t));
        m3 = fmaxf(m3, __shfl_xor_sync(0xffffffffu, m3, t));
    }
    float z0 = 0.f, z1 = 0.f, z2 = 0.f, z3 = 0.f;
    for (int j = s0 + lane; j < s1; j += 32) {
        float4 e = el4[srcs[j]];
        z0 += expf(lrelu(e.x + er.x, 0.2f) - m0);
        z1 += expf(lrelu(e.y + er.y, 0.2f) - m1);
        z2 += expf(lrelu(e.z + er.z, 0.2f) - m2);
        z3 += expf(lrelu(e.w + er.w, 0.2f) - m3);
    }
    #pragma unroll
    for (int t = 16; t; t >>= 1) {
        z0 += __shfl_xor_sync(0xffffffffu, z0, t);
        z1 += __shfl_xor_sync(0xffffffffu, z1, t);
        z2 += __shfl_xor_sync(0xffffffffu, z2, t);
        z3 += __shfl_xor_sync(0xffffffffu, z3, t);
    }
    int hsel = lane >> 3;   // 0..3
    float mS = (hsel == 0) ? m0 : (hsel == 1) ? m1 : (hsel == 2) ? m2 : m3;
    float zS = (hsel == 0) ? z0 : (hsel == 1) ? z1 : (hsel == 2) ? z2 : z3;
    float erS = (hsel == 0) ? er.x : (hsel == 1) ? er.y : (hsel == 2) ? er.z : er.w;
    float iS = 1.f / zS;

    float4 acc = make_float4(0.f, 0.f, 0.f, 0.f);
    for (int j = s0; j < s1; j++) {
        int s = srcs[j];
        float4 e = el4[s];
        float eS = (hsel == 0) ? e.x : (hsel == 1) ? e.y : (hsel == 2) ? e.z : e.w;
        float a = expf(lrelu(eS + erS, 0.2f) - mS) * iS;
        const float4* row = (const float4*)(hs + (size_t)s * 128);
        float4 v = row[lane];
        acc.x += a * v.x; acc.y += a * v.y; acc.z += a * v.z; acc.w += a * v.w;
    }
    o[lane] = acc;
}

// ---------------- BatchNorm ----------------
__global__ void k_bnstats(const float* __restrict__ x, float* __restrict__ stats, int n) {
    int c = threadIdx.x;
    float s = 0.f, q = 0.f;
    for (int r = blockIdx.x; r < n; r += gridDim.x) {
        float v = x[(size_t)r * 256 + c];
        s += v;
        q += v * v;
    }
    atomicAdd(&stats[c], s);
    atomicAdd(&stats[256 + c], q);
}

// BN apply + activation + fused bf16 hi/lo split for next layer's GEMM
__global__ void k_bnapply(const float* __restrict__ x, float* __restrict__ y,
                          __nv_bfloat16* __restrict__ yh, __nv_bfloat16* __restrict__ yl,
                          const float* __restrict__ bn, const float* __restrict__ stats,
                          int L, int n, int use_tanh) {
    int c = threadIdx.x;
    float mu = stats[c] / (float)n;
    float var = stats[256 + c] / (float)n - mu * mu;
    float gamma = bn[(L * 2 + 0) * 256 + c];
    float beta  = bn[(L * 2 + 1) * 256 + c];
    float sc = gamma * rsqrtf(var + 1e-5f);
    float sh = beta - mu * sc;
    for (int r = blockIdx.x; r < n; r += gridDim.x) {
        size_t idx = (size_t)r * 256 + c;
        float v = sc * x[idx] + sh;
        v = use_tanh ? tanhf(v) : (v > 0.f ? v : 0.01f * v);
        y[idx] = v;
        __nv_bfloat16 h = __float2bfloat16_rn(v);
        yh[idx] = h;
        yl[idx] = __float2bfloat16_rn(v - __bfloat162float(h));
    }
}

// ---------------- host orchestration ----------------
static inline int wgrid(int nwarp) { return (nwarp * 32 + 255) / 256; }

struct Ptrs {
    float *hu, *hi, *hsu, *hsi, *nu, *ni;
    float *el_u, *el_i, *er_u, *er_i, *V, *stats;
    __nv_bfloat16 *Bh, *Bl, *Auh, *Aul, *Aih, *Ail;
    int *rp_i, *rp_u, *srcs_i, *srcs_u, *cur_i, *cur_u, *part;
};

static void get_ptrs(Ptrs& p) {
    cudaGetSymbolAddress((void**)&p.hu, g_hu);
    cudaGetSymbolAddress((void**)&p.hi, g_hi);
    cudaGetSymbolAddress((void**)&p.hsu, g_hsu);
    cudaGetSymbolAddress((void**)&p.hsi, g_hsi);
    cudaGetSymbolAddress((void**)&p.nu, g_nu);
    cudaGetSymbolAddress((void**)&p.ni, g_ni);
    cudaGetSymbolAddress((void**)&p.el_u, g_el_u);
    cudaGetSymbolAddress((void**)&p.el_i, g_el_i);
    cudaGetSymbolAddress((void**)&p.er_u, g_er_u);
    cudaGetSymbolAddress((void**)&p.er_i, g_er_i);
    cudaGetSymbolAddress((void**)&p.V, g_V);
    cudaGetSymbolAddress((void**)&p.stats, g_stats);
    cudaGetSymbolAddress((void**)&p.Bh, g_Bh);
    cudaGetSymbolAddress((void**)&p.Bl, g_Bl);
    cudaGetSymbolAddress((void**)&p.Auh, g_Auh);
    cudaGetSymbolAddress((void**)&p.Aul, g_Aul);
    cudaGetSymbolAddress((void**)&p.Aih, g_Aih);
    cudaGetSymbolAddress((void**)&p.Ail, g_Ail);
    cudaGetSymbolAddress((void**)&p.rp_i, g_rp_i);
    cudaGetSymbolAddress((void**)&p.rp_u, g_rp_u);
    cudaGetSymbolAddress((void**)&p.srcs_i, g_srcs_i);
    cudaGetSymbolAddress((void**)&p.srcs_u, g_srcs_u);
    cudaGetSymbolAddress((void**)&p.cur_i, g_cur_i);
    cudaGetSymbolAddress((void**)&p.cur_u, g_cur_u);
    cudaGetSymbolAddress((void**)&p.part, g_part);
}

#define SMEM256 (2 * (2 * 128 * 80 + 2 * 32 * (256 * 2 + 16)))
#define SMEM128 (2 * (2 * 128 * 80 + 2 * 32 * (128 * 2 + 16)))

static void gemm_el(const Ptrs& p, const __nv_bfloat16* Ah, const __nv_bfloat16* Al,
                    const float* W, const float* attA, float* C, float* el,
                    int M, int K, int F) {
    k_split<<<(K * F + 255) / 256, 256>>>(W, p.Bh, p.Bl, K * F);
    int gb = (M + 127) / 128;
    if (F == 256)
        k_mma_gemm<256, 64><<<gb, 512, SMEM256>>>(Ah, Al, p.Bh, p.Bl, attA, C, el, M, K);
    else
        k_mma_gemm<128, 32><<<gb, 256, SMEM128>>>(Ah, Al, p.Bh, p.Bl, attA, C, el, M, K);
}

static void scan(const int* cnt, int n, int* rp, int* part) {
    int nb = (n + 1023) / 1024;
    k_scan_blk<<<nb, 1024>>>(cnt, n, rp, part);
    k_scan_part<<<1, 64>>>(part, nb);
    k_scan_add<<<nb, 1024>>>(rp, part, n);
}

static void relation_pass(const Ptrs& p, const float* cu, const float* ci,
                          const float* Wui, const float* Aui,
                          const float* Wiu, const float* Aiu,
                          int fin, int F, int dh,
                          float* outu, float* outi) {
    gemm_el(p, p.Auh, p.Aul, Wui, Aui, p.hsu, p.el_u, NUSR, fin, F);
    gemm_el(p, p.Aih, p.Ail, Wiu, Aiu, p.hsi, p.el_i, NITM, fin, F);
    k_collapseV<<<(fin * 4 + 255) / 256, 256>>>(Wui, Aui, p.V, fin, F, dh);
    k_er<<<wgrid(NITM), 256>>>(ci, (const float4*)p.V, p.er_i, NITM, fin);
    k_collapseV<<<(fin * 4 + 255) / 256, 256>>>(Wiu, Aiu, p.V, fin, F, dh);
    k_er<<<wgrid(NUSR), 256>>>(cu, (const float4*)p.V, p.er_u, NUSR, fin);
    if (F == 256) {
        k_edge256<<<wgrid(NITM), 256>>>(p.rp_i, p.srcs_i, (const float4*)p.el_u,
                                        (const float4*)p.er_i, p.hsu, outi, NITM);
        k_edge256<<<wgrid(NUSR), 256>>>(p.rp_u, p.srcs_u, (const float4*)p.el_i,
                                        (const float4*)p.er_u, p.hsi, outu, NUSR);
    } else {
        k_edge128<<<wgrid(NITM), 256>>>(p.rp_i, p.srcs_i, (const float4*)p.el_u,
                                        (const float4*)p.er_i, p.hsu, outi, NITM);
        k_edge128<<<wgrid(NUSR), 256>>>(p.rp_u, p.srcs_u, (const float4*)p.el_i,
                                        (const float4*)p.er_u, p.hsi, outu, NUSR);
    }
}

extern "C" void kernel_launch(void* const* d_in, const int* in_sizes, int n_in,
                              void* d_out, int out_size) {
    Ptrs p;
    get_ptrs(p);
    cudaFuncSetAttribute(k_mma_gemm<256, 64>,
                         cudaFuncAttributeMaxDynamicSharedMemorySize, SMEM256);
    cudaFuncSetAttribute(k_mma_gemm<128, 32>,
                         cudaFuncAttributeMaxDynamicSharedMemorySize, SMEM128);

    const float* x_user = (const float*)d_in[0];
    const float* x_item = (const float*)d_in[1];
    const int*   eu     = (const int*)d_in[2];
    const int*   ei     = (const int*)d_in[3];

    bool dictOrder = (in_sizes[5] < 10000);
    const float *Wui[4], *Aui[4], *Wiu[4], *Aiu[4];
    for (int L = 0; L < 4; L++) {
        if (dictOrder) {
            Wui[L] = (const float*)d_in[4 + L * 4 + 0];
            Aui[L] = (const float*)d_in[4 + L * 4 + 1];
            Wiu[L] = (const float*)d_in[4 + L * 4 + 2];
            Aiu[L] = (const float*)d_in[4 + L * 4 + 3];
        } else {
            Wui[L] = (const float*)d_in[4 + L * 4 + 0];
            Wiu[L] = (const float*)d_in[4 + L * 4 + 1];
            Aui[L] = (const float*)d_in[4 + L * 4 + 2];
            Aiu[L] = (const float*)d_in[4 + L * 4 + 3];
        }
    }
    const float* bn_u = (const float*)d_in[20];
    const float* bn_i = (const float*)d_in[21];
    float* out = (float*)d_out;

    // ---- CSR build ----
    k_zeroi<<<(NUSR + 255) / 256, 256>>>(p.cur_u, NUSR);
    k_zeroi<<<(NITM + 255) / 256, 256>>>(p.cur_i, NITM);
    k_count<<<(NEDG + 255) / 256, 256>>>(eu, ei, p.cur_u, p.cur_i);
    scan(p.cur_i, NITM, p.rp_i, p.part);
    scan(p.cur_u, NUSR, p.rp_u, p.part);
    k_copyi<<<(NITM + 255) / 256, 256>>>(p.rp_i, p.cur_i, NITM);
    k_copyi<<<(NUSR + 255) / 256, 256>>>(p.rp_u, p.cur_u, NUSR);
    k_scatter<<<(NEDG + 255) / 256, 256>>>(eu, ei, p.cur_u, p.cur_i, p.srcs_u, p.srcs_i);

    // ---- layer-0 input split ----
    k_split<<<(NUSR * FIN0 + 255) / 256, 256>>>(x_user, p.Auh, p.Aul, NUSR * FIN0);
    k_split<<<(NITM * FIN0 + 255) / 256, 256>>>(x_item, p.Aih, p.Ail, NITM * FIN0);

    // ---- hidden layers 0..2 ----
    const float* cu = x_user;
    const float* ci = x_item;
    int fin = FIN0;
    for (int L = 0; L < 3; L++) {
        relation_pass(p, cu, ci, Wui[L], Aui[L], Wiu[L], Aiu[L],
                      fin, 256, 64, p.nu, p.ni);
        int tanh_act = (L == 2) ? 1 : 0;
        k_zerof<<<2, 256>>>(p.stats, 512);
        k_bnstats<<<256, 256>>>(p.nu, p.stats, NUSR);
        k_bnapply<<<256, 256>>>(p.nu, p.hu, p.Auh, p.Aul, bn_u, p.stats, L, NUSR, tanh_act);
        k_zerof<<<2, 256>>>(p.stats, 512);
        k_bnstats<<<256, 256>>>(p.ni, p.stats, NITM);
        k_bnapply<<<256, 256>>>(p.ni, p.hi, p.Aih, p.Ail, bn_i, p.stats, L, NITM, tanh_act);
        cu = p.hu;
        ci = p.hi;
        fin = FHID;
    }

    // ---- output layer 3 ----
    relation_pass(p, cu, ci, Wui[3], Aui[3], Wiu[3], Aiu[3],
                  256, 128, 32,
                  out, out + (size_t)NUSR * 128);
    (void)n_in; (void)out_size;
}

// round 6
// speedup vs baseline: 1.5086x; 1.1364x over previous
#include <cuda_runtime.h>
#include <cuda_bf16.h>
#include <math.h>
#include <stddef.h>
#include <stdint.h>

// ---------------- problem constants ----------------
#define NUSR 50000
#define NITM 20000
#define NEDG 400000
#define FIN0 128
#define FHID 256
#define NHEAD 4

// ---------------- device scratch (no allocs allowed) ----------------
__device__ float g_hu [(size_t)NUSR * FHID];
__device__ float g_hi [(size_t)NITM * FHID];
__device__ float g_hsu[(size_t)NUSR * FHID];
__device__ float g_hsi[(size_t)NITM * FHID];
__device__ float g_nu [(size_t)NUSR * FHID];
__device__ float g_ni [(size_t)NITM * FHID];
__device__ float g_el_u[NUSR * 4];
__device__ float g_el_i[NITM * 4];
__device__ float g_er_u[NUSR * 4];
__device__ float g_er_i[NITM * 4];
__device__ int   g_rp_i[NITM + 1];
__device__ int   g_rp_u[NUSR + 1];
__device__ int   g_srcs_i[NEDG];
__device__ int   g_srcs_u[NEDG];
__device__ int   g_cur_i[NITM];
__device__ int   g_cur_u[NUSR];
__device__ float g_V1[FHID * NHEAD];
__device__ float g_V2[FHID * NHEAD];
__device__ float g_stats_i[2 * FHID];
__device__ float g_stats_u[2 * FHID];
__device__ int   g_part[64];
__device__ __nv_bfloat16 g_Bh1[FHID * FHID];
__device__ __nv_bfloat16 g_Bl1[FHID * FHID];
__device__ __nv_bfloat16 g_Bh2[FHID * FHID];
__device__ __nv_bfloat16 g_Bl2[FHID * FHID];
__device__ __nv_bfloat16 g_Auh[(size_t)NUSR * FHID];
__device__ __nv_bfloat16 g_Aul[(size_t)NUSR * FHID];
__device__ __nv_bfloat16 g_Aih[(size_t)NITM * FHID];
__device__ __nv_bfloat16 g_Ail[(size_t)NITM * FHID];

// ---------------- PTX helpers (baseline features only) ----------------
__device__ __forceinline__ uint32_t smem_u32(const void* p) {
    uint32_t a;
    asm("{ .reg .u64 t; cvta.to.shared.u64 t, %1; cvt.u32.u64 %0, t; }"
        : "=r"(a) : "l"(p));
    return a;
}
__device__ __forceinline__ void ldsm4(uint32_t* r, uint32_t addr) {
    asm volatile("ldmatrix.sync.aligned.m8n8.x4.shared.b16 {%0,%1,%2,%3}, [%4];"
        : "=r"(r[0]), "=r"(r[1]), "=r"(r[2]), "=r"(r[3]) : "r"(addr));
}
__device__ __forceinline__ void ldsm4t(uint32_t* r, uint32_t addr) {
    asm volatile("ldmatrix.sync.aligned.m8n8.x4.trans.shared.b16 {%0,%1,%2,%3}, [%4];"
        : "=r"(r[0]), "=r"(r[1]), "=r"(r[2]), "=r"(r[3]) : "r"(addr));
}
__device__ __forceinline__ void mma16816(float* c, const uint32_t* a,
                                         uint32_t b0, uint32_t b1) {
    asm volatile(
        "mma.sync.aligned.m16n8k16.row.col.f32.bf16.bf16.f32 "
        "{%0,%1,%2,%3}, {%4,%5,%6,%7}, {%8,%9}, {%0,%1,%2,%3};"
        : "+f"(c[0]), "+f"(c[1]), "+f"(c[2]), "+f"(c[3])
        : "r"(a[0]), "r"(a[1]), "r"(a[2]), "r"(a[3]), "r"(b0), "r"(b1));
}
#define CPA16(dst, src) \
    asm volatile("cp.async.cg.shared.global [%0], [%1], 16;" \
                 :: "r"(dst), "l"(src))
#define CP_COMMIT() asm volatile("cp.async.commit_group;")
#define CP_WAIT1()  asm volatile("cp.async.wait_group 1;" ::: "memory")
#define CP_WAIT0()  asm volatile("cp.async.wait_group 0;" ::: "memory")

// ---------------- tiny utility kernels ----------------
__global__ void k_noop() {}
__global__ void k_zeroi(int* p, int n) {
    int i = blockIdx.x * blockDim.x + threadIdx.x;
    if (i < n) p[i] = 0;
}
__global__ void k_zerof(float* p, int n) {
    int i = blockIdx.x * blockDim.x + threadIdx.x;
    if (i < n) p[i] = 0.f;
}
__global__ void k_copyi(const int* __restrict__ a, int* __restrict__ b, int n) {
    int i = blockIdx.x * blockDim.x + threadIdx.x;
    if (i < n) b[i] = a[i];
}

// ---------------- CSR construction ----------------
__global__ void k_count(const int* __restrict__ eu, const int* __restrict__ ei,
                        int* cu, int* ci) {
    int k = blockIdx.x * blockDim.x + threadIdx.x;
    if (k < NEDG) {
        atomicAdd(&ci[ei[k]], 1);
        atomicAdd(&cu[eu[k]], 1);
    }
}
__global__ void k_scan_blk(const int* __restrict__ cnt, int n,
                           int* __restrict__ rp, int* __restrict__ part) {
    __shared__ int ws[32];
    int tid = threadIdx.x;
    int i = blockIdx.x * 1024 + tid;
    int v = (i < n) ? cnt[i] : 0;
    int lane = tid & 31, w = tid >> 5;
    int x = v;
    #pragma unroll
    for (int o = 1; o < 32; o <<= 1) {
        int y = __shfl_up_sync(0xffffffffu, x, o);
        if (lane >= o) x += y;
    }
    if (lane == 31) ws[w] = x;
    __syncthreads();
    if (w == 0) {
        int t = ws[lane];
        #pragma unroll
        for (int o = 1; o < 32; o <<= 1) {
            int y = __shfl_up_sync(0xffffffffu, t, o);
            if (lane >= o) t += y;
        }
        ws[lane] = t;
    }
    __syncthreads();
    int incl = x + (w > 0 ? ws[w - 1] : 0);
    if (i < n) rp[i + 1] = incl;
    if (tid == 1023) part[blockIdx.x] = incl;
}
__global__ void k_scan_part(int* part, int nb) {
    __shared__ int w0sum;
    int tid = threadIdx.x;
    int v = (tid < nb) ? part[tid] : 0;
    int lane = tid & 31, w = tid >> 5;
    int x = v;
    #pragma unroll
    for (int o = 1; o < 32; o <<= 1) {
        int y = __shfl_up_sync(0xffffffffu, x, o);
        if (lane >= o) x += y;
    }
    if (w == 0 && lane == 31) w0sum = x;
    __syncthreads();
    int incl = x + (w ? w0sum : 0);
    if (tid < nb) part[tid] = incl - v;
}
__global__ void k_scan_add(int* __restrict__ rp, const int* __restrict__ part, int n) {
    int i = blockIdx.x * 1024 + threadIdx.x;
    if (i < n) rp[i + 1] += part[blockIdx.x];
    if (i == 0) rp[0] = 0;
}
__global__ void k_scatter(const int* __restrict__ eu, const int* __restrict__ ei,
                          int* cu, int* ci,
                          int* __restrict__ su, int* __restrict__ si) {
    int k = blockIdx.x * blockDim.x + threadIdx.x;
    if (k < NEDG) {
        int u = eu[k], it = ei[k];
        int p = atomicAdd(&ci[it], 1);
        si[p] = u;
        int q = atomicAdd(&cu[u], 1);
        su[q] = it;
    }
}

// ---------------- elementwise fp32 -> bf16 hi/lo split ----------------
__global__ void k_split(const float* __restrict__ X, __nv_bfloat16* __restrict__ xh,
                        __nv_bfloat16* __restrict__ xl, int total) {
    int id = blockIdx.x * blockDim.x + threadIdx.x;
    if (id >= total) return;
    float v = X[id];
    __nv_bfloat16 h = __float2bfloat16_rn(v);
    xh[id] = h;
    xl[id] = __float2bfloat16_rn(v - __bfloat162float(h));
}

// ---------------- tensor-core GEMM + fused el epilogue ----------------
template <int BN, int DH>
__global__ void __launch_bounds__((BN == 256) ? 512 : 256, 1)
k_mma_gemm(const __nv_bfloat16* __restrict__ Ah, const __nv_bfloat16* __restrict__ Al,
           const __nv_bfloat16* __restrict__ Bh, const __nv_bfloat16* __restrict__ Bl,
           const float* __restrict__ attA,
           float* __restrict__ C, float* __restrict__ el, int M, int K) {
    constexpr int NT = (BN == 256) ? 512 : 256;
    constexpr int SBSTR = BN * 2 + 16;
    constexpr int ASZ = 128 * 80;
    constexpr int BOFF = 2 * ASZ;
    constexpr int BSZ = 32 * SBSTR;
    constexpr int STAGE = BOFF + 2 * BSZ;
    constexpr int NBC = 32 * (BN / 8);

    extern __shared__ char smem[];
    uint32_t sb = smem_u32(smem);
    int tid = threadIdx.x;
    int wid = tid >> 5, lane = tid & 31;
    int wm = wid & 3, wn = wid >> 2;
    int bm = blockIdx.x * 128;

    float acc[2][8][4];
    #pragma unroll
    for (int i = 0; i < 2; i++)
        #pragma unroll
        for (int j = 0; j < 8; j++)
            #pragma unroll
            for (int q = 0; q < 4; q++) acc[i][j][q] = 0.f;

    int nch = K >> 5;

    auto load_stage = [&](int st, int kc) {
        uint32_t sbase = sb + st * STAGE;
        int k0 = kc << 5;
        #pragma unroll
        for (int c = tid; c < 512; c += NT) {
            int row = c >> 2, q = c & 3;
            int gr = bm + row;
            gr = gr < M ? gr : M - 1;
            size_t gi = (size_t)gr * K + k0 + q * 8;
            uint32_t d = sbase + row * 80 + q * 16;
            CPA16(d, Ah + gi);
            CPA16(d + ASZ, Al + gi);
        }
        #pragma unroll
        for (int c = tid; c < NBC; c += NT) {
            int k = c / (BN / 8), seg = c % (BN / 8);
            size_t gi = (size_t)(k0 + k) * BN + seg * 8;
            uint32_t d = sbase + BOFF + k * SBSTR + seg * 16;
            CPA16(d, Bh + gi);
            CPA16(d + BSZ, Bl + gi);
        }
        CP_COMMIT();
    };

    load_stage(0, 0);
    for (int kc = 0; kc < nch; kc++) {
        int cur = kc & 1;
        if (kc + 1 < nch) {
            load_stage(1 - cur, kc + 1);
            CP_WAIT1();
        } else {
            CP_WAIT0();
        }
        __syncthreads();
        uint32_t abase = sb + cur * STAGE;
        #pragma unroll
        for (int s = 0; s < 2; s++) {
            uint32_t Af[2][4], Alf[2][4];
            #pragma unroll
            for (int mt = 0; mt < 2; mt++) {
                uint32_t ad = abase +
                    (uint32_t)(wm * 32 + mt * 16 + (lane & 15)) * 80 +
                    s * 32 + (lane >> 4) * 16;
                ldsm4(Af[mt], ad);
                ldsm4(Alf[mt], ad + ASZ);
            }
            #pragma unroll
            for (int np = 0; np < 4; np++) {
                int g = lane >> 3, r = lane & 7;
                int kk = s * 16 + (g & 1) * 8 + r;
                int nn = wn * 64 + np * 16 + (g >> 1) * 8;
                uint32_t bd = abase + BOFF + (uint32_t)kk * SBSTR + nn * 2;
                uint32_t bh4[4], bl4[4];
                ldsm4t(bh4, bd);
                ldsm4t(bl4, bd + BSZ);
                #pragma unroll
                for (int mt = 0; mt < 2; mt++)
                    #pragma unroll
                    for (int sub = 0; sub < 2; sub++) {
                        float* a = acc[mt][np * 2 + sub];
                        mma16816(a, Af[mt], bh4[2 * sub], bh4[2 * sub + 1]);
                        mma16816(a, Af[mt], bl4[2 * sub], bl4[2 * sub + 1]);
                        mma16816(a, Alf[mt], bh4[2 * sub], bh4[2 * sub + 1]);
                    }
            }
        }
        __syncthreads();
    }

    constexpr int HPW = 64 / DH;
    int grp = lane >> 2, tq = lane & 3;
    #pragma unroll
    for (int mt = 0; mt < 2; mt++) {
        int r0 = bm + wm * 32 + mt * 16 + grp;
        int r1 = r0 + 8;
        #pragma unroll
        for (int nt = 0; nt < 8; nt++) {
            int col = wn * 64 + nt * 8 + tq * 2;
            if (r0 < M)
                *(float2*)(C + (size_t)r0 * BN + col) =
                    make_float2(acc[mt][nt][0], acc[mt][nt][1]);
            if (r1 < M)
                *(float2*)(C + (size_t)r1 * BN + col) =
                    make_float2(acc[mt][nt][2], acc[mt][nt][3]);
        }
        float s0[HPW], s1[HPW];
        #pragma unroll
        for (int p = 0; p < HPW; p++) { s0[p] = 0.f; s1[p] = 0.f; }
        #pragma unroll
        for (int nt = 0; nt < 8; nt++) {
            int part = (nt * 8) / DH;
            int col = wn * 64 + nt * 8 + tq * 2;
            float c0 = attA[col], c1 = attA[col + 1];
            s0[part] += c0 * acc[mt][nt][0] + c1 * acc[mt][nt][1];
            s1[part] += c0 * acc[mt][nt][2] + c1 * acc[mt][nt][3];
        }
        #pragma unroll
        for (int p = 0; p < HPW; p++) {
            s0[p] += __shfl_xor_sync(0xffffffffu, s0[p], 1);
            s0[p] += __shfl_xor_sync(0xffffffffu, s0[p], 2);
            s1[p] += __shfl_xor_sync(0xffffffffu, s1[p], 1);
            s1[p] += __shfl_xor_sync(0xffffffffu, s1[p], 2);
            if (tq == 0) {
                int h = wn * HPW + p;
                if (r0 < M) el[r0 * 4 + h] = s0[p];
                if (r1 < M) el[r1 * 4 + h] = s1[p];
            }
        }
    }
}

// ---------------- V[k,h] = sum_d W[k, h*dh+d] * A1[h,d] ----------------
__global__ void k_collapseV(const float* __restrict__ W, const float* __restrict__ A,
                            float* __restrict__ V, int fin, int F, int dh) {
    int t = blockIdx.x * blockDim.x + threadIdx.x;
    if (t >= fin * NHEAD) return;
    int k = t >> 2, h = t & 3;
    const float* A1 = A + NHEAD * dh;
    float s = 0.f;
    for (int d = 0; d < dh; d++)
        s += W[(size_t)k * F + h * dh + d] * A1[h * dh + d];
    V[t] = s;
}

// ---------------- er[n,:] = X[n,:] @ V ----------------
__global__ void k_er(const float* __restrict__ X, const float4* __restrict__ V4,
                     float* __restrict__ er, int n, int fin) {
    int w = (blockIdx.x * blockDim.x + threadIdx.x) >> 5;
    int lane = threadIdx.x & 31;
    if (w >= n) return;
    const float* x = X + (size_t)w * fin;
    float a0 = 0.f, a1 = 0.f, a2 = 0.f, a3 = 0.f;
    for (int k = lane; k < fin; k += 32) {
        float xv = x[k];
        float4 v = V4[k];
        a0 += xv * v.x; a1 += xv * v.y; a2 += xv * v.z; a3 += xv * v.w;
    }
    #pragma unroll
    for (int o = 16; o; o >>= 1) {
        a0 += __shfl_xor_sync(0xffffffffu, a0, o);
        a1 += __shfl_xor_sync(0xffffffffu, a1, o);
        a2 += __shfl_xor_sync(0xffffffffu, a2, o);
        a3 += __shfl_xor_sync(0xffffffffu, a3, o);
    }
    if (lane == 0) {
        er[w * 4 + 0] = a0; er[w * 4 + 1] = a1;
        er[w * 4 + 2] = a2; er[w * 4 + 3] = a3;
    }
}

__device__ __forceinline__ float lrelu(float x, float s) { return x > 0.f ? x : s * x; }

// ---------------- fused segment softmax + aggregation, F=256 ----------------
__global__ void k_edge256(const int* __restrict__ rp, const int* __restrict__ srcs,
                          const float4* __restrict__ el4, const float4* __restrict__ er4,
                          const float* __restrict__ hs, float* __restrict__ out,
                          int ndst) {
    int w = (blockIdx.x * blockDim.x + threadIdx.x) >> 5;
    int lane = threadIdx.x & 31;
    if (w >= ndst) return;
    int s0 = rp[w], s1 = rp[w + 1];
    float4* o = (float4*)(out + (size_t)w * 256);
    if (s0 == s1) {
        float4 z = make_float4(0.f, 0.f, 0.f, 0.f);
        o[lane] = z;
        o[lane + 32] = z;
        return;
    }
    float4 er = er4[w];
    float m0 = -1e30f, m1 = -1e30f, m2 = -1e30f, m3 = -1e30f;
    for (int j = s0 + lane; j < s1; j += 32) {
        float4 e = el4[srcs[j]];
        m0 = fmaxf(m0, lrelu(e.x + er.x, 0.2f));
        m1 = fmaxf(m1, lrelu(e.y + er.y, 0.2f));
        m2 = fmaxf(m2, lrelu(e.z + er.z, 0.2f));
        m3 = fmaxf(m3, lrelu(e.w + er.w, 0.2f));
    }
    #pragma unroll
    for (int t = 16; t; t >>= 1) {
        m0 = fmaxf(m0, __shfl_xor_sync(0xffffffffu, m0, t));
        m1 = fmaxf(m1, __shfl_xor_sync(0xffffffffu, m1, t));
        m2 = fmaxf(m2, __shfl_xor_sync(0xffffffffu, m2, t));
        m3 = fmaxf(m3, __shfl_xor_sync(0xffffffffu, m3, t));
    }
    float z0 = 0.f, z1 = 0.f, z2 = 0.f, z3 = 0.f;
    for (int j = s0 + lane; j < s1; j += 32) {
        float4 e = el4[srcs[j]];
        z0 += expf(lrelu(e.x + er.x, 0.2f) - m0);
        z1 += expf(lrelu(e.y + er.y, 0.2f) - m1);
        z2 += expf(lrelu(e.z + er.z, 0.2f) - m2);
        z3 += expf(lrelu(e.w + er.w, 0.2f) - m3);
    }
    #pragma unroll
    for (int t = 16; t; t >>= 1) {
        z0 += __shfl_xor_sync(0xffffffffu, z0, t);
        z1 += __shfl_xor_sync(0xffffffffu, z1, t);
        z2 += __shfl_xor_sync(0xffffffffu, z2, t);
        z3 += __shfl_xor_sync(0xffffffffu, z3, t);
    }
    bool loHalf = lane < 16;
    float mA = loHalf ? m0 : m1, mB = loHalf ? m2 : m3;
    float iA = 1.f / (loHalf ? z0 : z1), iB = 1.f / (loHalf ? z2 : z3);
    float erA = loHalf ? er.x : er.y, erB = loHalf ? er.z : er.w;

    float4 acc0 = make_float4(0.f, 0.f, 0.f, 0.f);
    float4 acc1 = make_float4(0.f, 0.f, 0.f, 0.f);
    for (int j = s0; j < s1; j++) {
        int s = srcs[j];
        float4 e = el4[s];
        float eA = loHalf ? e.x : e.y, eB = loHalf ? e.z : e.w;
        float a0 = expf(lrelu(eA + erA, 0.2f) - mA) * iA;
        float a1 = expf(lrelu(eB + erB, 0.2f) - mB) * iB;
        const float4* row = (const float4*)(hs + (size_t)s * 256);
        float4 v0 = row[lane];
        float4 v1 = row[lane + 32];
        acc0.x += a0 * v0.x; acc0.y += a0 * v0.y; acc0.z += a0 * v0.z; acc0.w += a0 * v0.w;
        acc1.x += a1 * v1.x; acc1.y += a1 * v1.y; acc1.z += a1 * v1.z; acc1.w += a1 * v1.w;
    }
    o[lane] = acc0;
    o[lane + 32] = acc1;
}

// ---------------- fused segment softmax + aggregation, F=128 ----------------
__global__ void k_edge128(const int* __restrict__ rp, const int* __restrict__ srcs,
                          const float4* __restrict__ el4, const float4* __restrict__ er4,
                          const float* __restrict__ hs, float* __restrict__ out,
                          int ndst) {
    int w = (blockIdx.x * blockDim.x + threadIdx.x) >> 5;
    int lane = threadIdx.x & 31;
    if (w >= ndst) return;
    int s0 = rp[w], s1 = rp[w + 1];
    float4* o = (float4*)(out + (size_t)w * 128);
    if (s0 == s1) {
        o[lane] = make_float4(0.f, 0.f, 0.f, 0.f);
        return;
    }
    float4 er = er4[w];
    float m0 = -1e30f, m1 = -1e30f, m2 = -1e30f, m3 = -1e30f;
    for (int j = s0 + lane; j < s1; j += 32) {
        float4 e = el4[srcs[j]];
        m0 = fmaxf(m0, lrelu(e.x + er.x, 0.2f));
        m1 = fmaxf(m1, lrelu(e.y + er.y, 0.2f));
        m2 = fmaxf(m2, lrelu(e.z + er.z, 0.2f));
        m3 = fmaxf(m3, lrelu(e.w + er.w, 0.2f));
    }
    #pragma unroll
    for (int t = 16; t; t >>= 1) {
        m0 = fmaxf(m0, __shfl_xor_sync(0xffffffffu, m0, t));
        m1 = fmaxf(m1, __shfl_xor_sync(0xffffffffu, m1, t));
        m2 = fmaxf(m2, __shfl_xor_sync(0xffffffffu, m2, t));
        m3 = fmaxf(m3, __shfl_xor_sync(0xffffffffu, m3, t));
    }
    float z0 = 0.f, z1 = 0.f, z2 = 0.f, z3 = 0.f;
    for (int j = s0 + lane; j < s1; j += 32) {
        float4 e = el4[srcs[j]];
        z0 += expf(lrelu(e.x + er.x, 0.2f) - m0);
        z1 += expf(lrelu(e.y + er.y, 0.2f) - m1);
        z2 += expf(lrelu(e.z + er.z, 0.2f) - m2);
        z3 += expf(lrelu(e.w + er.w, 0.2f) - m3);
    }
    #pragma unroll
    for (int t = 16; t; t >>= 1) {
        z0 += __shfl_xor_sync(0xffffffffu, z0, t);
        z1 += __shfl_xor_sync(0xffffffffu, z1, t);
        z2 += __shfl_xor_sync(0xffffffffu, z2, t);
        z3 += __shfl_xor_sync(0xffffffffu, z3, t);
    }
    int hsel = lane >> 3;
    float mS = (hsel == 0) ? m0 : (hsel == 1) ? m1 : (hsel == 2) ? m2 : m3;
    float zS = (hsel == 0) ? z0 : (hsel == 1) ? z1 : (hsel == 2) ? z2 : z3;
    float erS = (hsel == 0) ? er.x : (hsel == 1) ? er.y : (hsel == 2) ? er.z : er.w;
    float iS = 1.f / zS;

    float4 acc = make_float4(0.f, 0.f, 0.f, 0.f);
    for (int j = s0; j < s1; j++) {
        int s = srcs[j];
        float4 e = el4[s];
        float eS = (hsel == 0) ? e.x : (hsel == 1) ? e.y : (hsel == 2) ? e.z : e.w;
        float a = expf(lrelu(eS + erS, 0.2f) - mS) * iS;
        const float4* row = (const float4*)(hs + (size_t)s * 128);
        float4 v = row[lane];
        acc.x += a * v.x; acc.y += a * v.y; acc.z += a * v.z; acc.w += a * v.w;
    }
    o[lane] = acc;
}

// ---------------- BatchNorm ----------------
__global__ void k_bnstats(const float* __restrict__ x, float* __restrict__ stats, int n) {
    int c = threadIdx.x;
    float s = 0.f, q = 0.f;
    for (int r = blockIdx.x; r < n; r += gridDim.x) {
        float v = x[(size_t)r * 256 + c];
        s += v;
        q += v * v;
    }
    atomicAdd(&stats[c], s);
    atomicAdd(&stats[256 + c], q);
}

__global__ void k_bnapply(const float* __restrict__ x, float* __restrict__ y,
                          __nv_bfloat16* __restrict__ yh, __nv_bfloat16* __restrict__ yl,
                          const float* __restrict__ bn, const float* __restrict__ stats,
                          int L, int n, int use_tanh) {
    int c = threadIdx.x;
    float mu = stats[c] / (float)n;
    float var = stats[256 + c] / (float)n - mu * mu;
    float gamma = bn[(L * 2 + 0) * 256 + c];
    float beta  = bn[(L * 2 + 1) * 256 + c];
    float sc = gamma * rsqrtf(var + 1e-5f);
    float sh = beta - mu * sc;
    for (int r = blockIdx.x; r < n; r += gridDim.x) {
        size_t idx = (size_t)r * 256 + c;
        float v = sc * x[idx] + sh;
        v = use_tanh ? tanhf(v) : (v > 0.f ? v : 0.01f * v);
        y[idx] = v;
        __nv_bfloat16 h = __float2bfloat16_rn(v);
        yh[idx] = h;
        yl[idx] = __float2bfloat16_rn(v - __bfloat162float(h));
    }
}

// ---------------- static stream/event setup (pre-checkpoint) ----------------
namespace {
struct StreamInit {
    cudaStream_t s2 = 0;
    cudaEvent_t ev[32];
    bool ok = false;
    StreamInit() {
        if (cudaStreamCreateWithFlags(&s2, cudaStreamNonBlocking) != cudaSuccess) return;
        for (int i = 0; i < 32; i++)
            if (cudaEventCreateWithFlags(&ev[i], cudaEventDisableTiming) != cudaSuccess)
                return;
        k_noop<<<1, 32>>>();
        k_noop<<<1, 32, 0, s2>>>();
        for (int i = 0; i < 32; i++) cudaEventRecord(ev[i], (i & 1) ? s2 : 0);
        if (cudaDeviceSynchronize() != cudaSuccess) return;
        if (cudaGetLastError() != cudaSuccess) return;
        ok = true;
    }
};
StreamInit g_si;
}

// ---------------- host orchestration ----------------
static inline int wgrid(int nwarp) { return (nwarp * 32 + 255) / 256; }

struct Ptrs {
    float *hu, *hi, *hsu, *hsi, *nu, *ni;
    float *el_u, *el_i, *er_u, *er_i, *V1, *V2, *stats_i, *stats_u;
    __nv_bfloat16 *Bh1, *Bl1, *Bh2, *Bl2, *Auh, *Aul, *Aih, *Ail;
    int *rp_i, *rp_u, *srcs_i, *srcs_u, *cur_i, *cur_u, *part;
};

static void get_ptrs(Ptrs& p) {
    cudaGetSymbolAddress((void**)&p.hu, g_hu);
    cudaGetSymbolAddress((void**)&p.hi, g_hi);
    cudaGetSymbolAddress((void**)&p.hsu, g_hsu);
    cudaGetSymbolAddress((void**)&p.hsi, g_hsi);
    cudaGetSymbolAddress((void**)&p.nu, g_nu);
    cudaGetSymbolAddress((void**)&p.ni, g_ni);
    cudaGetSymbolAddress((void**)&p.el_u, g_el_u);
    cudaGetSymbolAddress((void**)&p.el_i, g_el_i);
    cudaGetSymbolAddress((void**)&p.er_u, g_er_u);
    cudaGetSymbolAddress((void**)&p.er_i, g_er_i);
    cudaGetSymbolAddress((void**)&p.V1, g_V1);
    cudaGetSymbolAddress((void**)&p.V2, g_V2);
    cudaGetSymbolAddress((void**)&p.stats_i, g_stats_i);
    cudaGetSymbolAddress((void**)&p.stats_u, g_stats_u);
    cudaGetSymbolAddress((void**)&p.Bh1, g_Bh1);
    cudaGetSymbolAddress((void**)&p.Bl1, g_Bl1);
    cudaGetSymbolAddress((void**)&p.Bh2, g_Bh2);
    cudaGetSymbolAddress((void**)&p.Bl2, g_Bl2);
    cudaGetSymbolAddress((void**)&p.Auh, g_Auh);
    cudaGetSymbolAddress((void**)&p.Aul, g_Aul);
    cudaGetSymbolAddress((void**)&p.Aih, g_Aih);
    cudaGetSymbolAddress((void**)&p.Ail, g_Ail);
    cudaGetSymbolAddress((void**)&p.rp_i, g_rp_i);
    cudaGetSymbolAddress((void**)&p.rp_u, g_rp_u);
    cudaGetSymbolAddress((void**)&p.srcs_i, g_srcs_i);
    cudaGetSymbolAddress((void**)&p.srcs_u, g_srcs_u);
    cudaGetSymbolAddress((void**)&p.cur_i, g_cur_i);
    cudaGetSymbolAddress((void**)&p.cur_u, g_cur_u);
    cudaGetSymbolAddress((void**)&p.part, g_part);
}

#define SMEM256 (2 * (2 * 128 * 80 + 2 * 32 * (256 * 2 + 16)))
#define SMEM128 (2 * (2 * 128 * 80 + 2 * 32 * (128 * 2 + 16)))

static void gemm_el(const __nv_bfloat16* Ah, const __nv_bfloat16* Al,
                    __nv_bfloat16* Bh, __nv_bfloat16* Bl,
                    const float* W, const float* attA, float* C, float* el,
                    int M, int K, int F, cudaStream_t st) {
    k_split<<<(K * F + 255) / 256, 256, 0, st>>>(W, Bh, Bl, K * F);
    int gb = (M + 127) / 128;
    if (F == 256)
        k_mma_gemm<256, 64><<<gb, 512, SMEM256, st>>>(Ah, Al, Bh, Bl, attA, C, el, M, K);
    else
        k_mma_gemm<128, 32><<<gb, 256, SMEM128, st>>>(Ah, Al, Bh, Bl, attA, C, el, M, K);
}

static void scan(const int* cnt, int n, int* rp, int* part, cudaStream_t st) {
    int nb = (n + 1023) / 1024;
    k_scan_blk<<<nb, 1024, 0, st>>>(cnt, n, rp, part);
    k_scan_part<<<1, 64, 0, st>>>(part, nb);
    k_scan_add<<<nb, 1024, 0, st>>>(rp, part, n);
}

extern "C" void kernel_launch(void* const* d_in, const int* in_sizes, int n_in,
                              void* d_out, int out_size) {
    Ptrs p;
    get_ptrs(p);
    cudaFuncSetAttribute(k_mma_gemm<256, 64>,
                         cudaFuncAttributeMaxDynamicSharedMemorySize, SMEM256);
    cudaFuncSetAttribute(k_mma_gemm<128, 32>,
                         cudaFuncAttributeMaxDynamicSharedMemorySize, SMEM128);

    const float* x_user = (const float*)d_in[0];
    const float* x_item = (const float*)d_in[1];
    const int*   eu     = (const int*)d_in[2];
    const int*   ei     = (const int*)d_in[3];

    bool dictOrder = (in_sizes[5] < 10000);
    const float *Wui[4], *Aui[4], *Wiu[4], *Aiu[4];
    for (int L = 0; L < 4; L++) {
        if (dictOrder) {
            Wui[L] = (const float*)d_in[4 + L * 4 + 0];
            Aui[L] = (const float*)d_in[4 + L * 4 + 1];
            Wiu[L] = (const float*)d_in[4 + L * 4 + 2];
            Aiu[L] = (const float*)d_in[4 + L * 4 + 3];
        } else {
            Wui[L] = (const float*)d_in[4 + L * 4 + 0];
            Wiu[L] = (const float*)d_in[4 + L * 4 + 1];
            Aui[L] = (const float*)d_in[4 + L * 4 + 2];
            Aiu[L] = (const float*)d_in[4 + L * 4 + 3];
        }
    }
    const float* bn_u = (const float*)d_in[20];
    const float* bn_i = (const float*)d_in[21];
    float* out = (float*)d_out;

    cudaStream_t SA = 0;
    cudaStream_t SB = g_si.ok ? g_si.s2 : (cudaStream_t)0;
    bool fork = g_si.ok;
    int ec = 0;
    auto REC = [&](cudaStream_t st) -> int {
        if (!fork) return -1;
        int i = ec++;
        cudaEventRecord(g_si.ev[i], st);
        return i;
    };
    auto WAITE = [&](cudaStream_t st, int i) {
        if (fork && i >= 0) cudaStreamWaitEvent(st, g_si.ev[i], 0);
    };

    // ---- capture-legal fork: SB must first wait on an event recorded in SA ----
    int evFork = REC(SA);
    WAITE(SB, evFork);

    // ---- CSR build on SB (now inside the capture) ----
    k_zeroi<<<(NUSR + 255) / 256, 256, 0, SB>>>(p.cur_u, NUSR);
    k_zeroi<<<(NITM + 255) / 256, 256, 0, SB>>>(p.cur_i, NITM);
    k_count<<<(NEDG + 255) / 256, 256, 0, SB>>>(eu, ei, p.cur_u, p.cur_i);
    scan(p.cur_i, NITM, p.rp_i, p.part, SB);
    scan(p.cur_u, NUSR, p.rp_u, p.part, SB);
    k_copyi<<<(NITM + 255) / 256, 256, 0, SB>>>(p.rp_i, p.cur_i, NITM);
    k_copyi<<<(NUSR + 255) / 256, 256, 0, SB>>>(p.rp_u, p.cur_u, NUSR);
    k_scatter<<<(NEDG + 255) / 256, 256, 0, SB>>>(eu, ei, p.cur_u, p.cur_i,
                                                  p.srcs_u, p.srcs_i);
    int evCSR = REC(SB);

    // ---- layer-0 input splits ----
    k_split<<<(NUSR * FIN0 + 255) / 256, 256, 0, SA>>>(x_user, p.Auh, p.Aul, NUSR * FIN0);
    k_split<<<(NITM * FIN0 + 255) / 256, 256, 0, SB>>>(x_item, p.Aih, p.Ail, NITM * FIN0);

    const float* cu = x_user;
    const float* ci = x_item;
    int fin = FIN0;
    for (int L = 0; L < 4; L++) {
        int F = (L == 3) ? 128 : 256;
        int dh = (L == 3) ? 32 : 64;
        float* outi = (L == 3) ? (out + (size_t)NUSR * 128) : p.ni;
        float* outu = (L == 3) ? out : p.nu;

        // A: user GEMM (+el_u), V_ui, er_i
        gemm_el(p.Auh, p.Aul, p.Bh1, p.Bl1, Wui[L], Aui[L], p.hsu, p.el_u,
                NUSR, fin, F, SA);
        k_collapseV<<<(fin * 4 + 255) / 256, 256, 0, SA>>>(Wui[L], Aui[L], p.V1,
                                                           fin, F, dh);
        k_er<<<wgrid(NITM), 256, 0, SA>>>(ci, (const float4*)p.V1, p.er_i, NITM, fin);
        int evAg = REC(SA);

        // B: item GEMM (+el_i), V_iu, er_u
        gemm_el(p.Aih, p.Ail, p.Bh2, p.Bl2, Wiu[L], Aiu[L], p.hsi, p.el_i,
                NITM, fin, F, SB);
        k_collapseV<<<(fin * 4 + 255) / 256, 256, 0, SB>>>(Wiu[L], Aiu[L], p.V2,
                                                           fin, F, dh);
        k_er<<<wgrid(NUSR), 256, 0, SB>>>(cu, (const float4*)p.V2, p.er_u, NUSR, fin);
        int evBg = REC(SB);

        // edges: item-dst on A, user-dst on B
        if (L == 0) WAITE(SA, evCSR);
        if (F == 256) {
            k_edge256<<<wgrid(NITM), 256, 0, SA>>>(p.rp_i, p.srcs_i,
                (const float4*)p.el_u, (const float4*)p.er_i, p.hsu, outi, NITM);
            k_edge256<<<wgrid(NUSR), 256, 0, SB>>>(p.rp_u, p.srcs_u,
                (const float4*)p.el_i, (const float4*)p.er_u, p.hsi, outu, NUSR);
        } else {
            k_edge128<<<wgrid(NITM), 256, 0, SA>>>(p.rp_i, p.srcs_i,
                (const float4*)p.el_u, (const float4*)p.er_i, p.hsu, outi, NITM);
            k_edge128<<<wgrid(NUSR), 256, 0, SB>>>(p.rp_u, p.srcs_u,
                (const float4*)p.el_i, (const float4*)p.er_u, p.hsi, outu, NUSR);
        }

        if (L < 3) {
            // BN item on A (writes Aih/Ail -> must wait for B's gemm_i read)
            k_zerof<<<2, 256, 0, SA>>>(p.stats_i, 512);
            k_bnstats<<<256, 256, 0, SA>>>(p.ni, p.stats_i, NITM);
            WAITE(SA, evBg);
            k_bnapply<<<256, 256, 0, SA>>>(p.ni, p.hi, p.Aih, p.Ail, bn_i,
                                           p.stats_i, L, NITM, (L == 2) ? 1 : 0);
            // BN user on B (writes Auh/Aul -> must wait for A's gemm_u read)
            k_zerof<<<2, 256, 0, SB>>>(p.stats_u, 512);
            k_bnstats<<<256, 256, 0, SB>>>(p.nu, p.stats_u, NUSR);
            WAITE(SB, evAg);
            k_bnapply<<<256, 256, 0, SB>>>(p.nu, p.hu, p.Auh, p.Aul, bn_u,
                                           p.stats_u, L, NUSR, (L == 2) ? 1 : 0);
            // layer-boundary cross joins
            int evAe = REC(SA);
            int evBe = REC(SB);
            WAITE(SA, evBe);
            WAITE(SB, evAe);
            cu = p.hu;
            ci = p.hi;
            fin = FHID;
        } else {
            // final join: everything funnels back into the capturing stream
            int evBf = REC(SB);
            WAITE(SA, evBf);
        }
    }
    (void)n_in; (void)out_size;
}